// round 1
// baseline (speedup 1.0000x reference)
#include <cuda_runtime.h>
#include <math.h>

#define BB 2
#define TT 4096
#define DD 1024
#define LL 2
#define HH 16
#define FF 4096
#define KK 2048
#define DHD 64
#define MROWS (BB*KK)   // 4096 (batch folded into M)

// ---------------- scratch (static device globals; no allocations) ----------------
__device__ float g_logits[BB*TT];
__device__ int   g_idx[BB*KK];
__device__ float g_gate[BB*KK];
__device__ float g_h[BB*KK*DD];
__device__ float g_a[BB*KK*DD];
__device__ float g_qkv[BB*KK*3*DD];
__device__ float g_attn[BB*KK*DD];
__device__ float g_ffn[(size_t)BB*KK*FF];

// ---------------- router ----------------
__global__ void router_kernel(const float* __restrict__ x,
                              const float* __restrict__ w,
                              const float* __restrict__ br) {
    int row  = blockIdx.x * 8 + (threadIdx.x >> 5);
    int lane = threadIdx.x & 31;
    const float4* xr = (const float4*)(x + (size_t)row * DD);
    const float4* wr = (const float4*)w;
    float s = 0.f;
#pragma unroll
    for (int i = 0; i < 8; i++) {
        int c = lane + i * 32;
        float4 a = xr[c], b = wr[c];
        s += a.x*b.x + a.y*b.y + a.z*b.z + a.w*b.w;
    }
#pragma unroll
    for (int o = 16; o; o >>= 1) s += __shfl_xor_sync(0xffffffffu, s, o);
    if (!lane) g_logits[row] = s + br[0];
}

// ---------------- exact top-K (K = T/2) via radix select + scan ----------------
__global__ void topk_kernel() {
    __shared__ unsigned key[TT];
    __shared__ int s_cnt;
    __shared__ int s_scan[1024];
    int b = blockIdx.x, tid = threadIdx.x;

    for (int t = tid; t < TT; t += 1024) {
        unsigned u = __float_as_uint(g_logits[b*TT + t]);
        u = (u & 0x80000000u) ? ~u : (u | 0x80000000u);   // order-preserving map
        key[t] = u;
    }
    __syncthreads();

    unsigned prefix = 0; int needed = KK;
    for (int bit = 31; bit >= 0; --bit) {
        if (!tid) s_cnt = 0;
        __syncthreads();
        unsigned cand = prefix | (1u << bit);
        unsigned mask = ~((1u << bit) - 1u);
        int loc = 0;
        for (int t = tid; t < TT; t += 1024) loc += ((key[t] & mask) == cand);
#pragma unroll
        for (int o = 16; o; o >>= 1) loc += __shfl_xor_sync(0xffffffffu, loc, o);
        if ((tid & 31) == 0) atomicAdd(&s_cnt, loc);
        __syncthreads();
        int c = s_cnt;
        if (needed <= c) prefix = cand; else needed -= c;
        __syncthreads();
    }
    // prefix = K-th largest key; take all > prefix, plus first `needed` ties by index.
    int base = tid * 4;
    int vals[4]; int run = 0;
#pragma unroll
    for (int i = 0; i < 4; i++) {
        unsigned k2 = key[base + i];
        int gt = (k2 > prefix), eq = (k2 == prefix);
        vals[i] = run;
        run += (gt << 16) | eq;
    }
    s_scan[tid] = run;
    __syncthreads();
    for (int off = 1; off < 1024; off <<= 1) {
        int v = (tid >= off) ? s_scan[tid - off] : 0;
        __syncthreads();
        s_scan[tid] += v;
        __syncthreads();
    }
    int excl = tid ? s_scan[tid - 1] : 0;
#pragma unroll
    for (int i = 0; i < 4; i++) {
        int t = base + i;
        unsigned k2 = key[t];
        int pre = excl + vals[i];
        int gtB = pre >> 16, eqB = pre & 0xFFFF;
        bool sel = (k2 > prefix) || (k2 == prefix && eqB < needed);
        if (sel) {
            int pos = gtB + min(eqB, needed);
            g_idx[b*KK + pos] = t;
            float lg = g_logits[b*TT + t];
            g_gate[b*KK + pos] = 1.f / (1.f + expf(-lg));
        }
    }
}

// ---------------- gather / scatter / output ----------------
__global__ void gather_kernel(const float* __restrict__ x) {
    int row = blockIdx.x;
    int b = row / KK;
    int t = g_idx[row];
    const float4* src = (const float4*)(x + ((size_t)b*TT + t) * DD);
    float4* dst = (float4*)(g_h + (size_t)row * DD);
    dst[threadIdx.x] = src[threadIdx.x];
}

__global__ void copy_out_kernel(const float* __restrict__ x, float* __restrict__ out) {
    size_t i = (size_t)blockIdx.x * 256 + threadIdx.x;
    ((float4*)out)[i] = ((const float4*)x)[i];
}

__global__ void scatter_kernel(float* __restrict__ out) {
    int row = blockIdx.x;
    int b = row / KK;
    int t = g_idx[row];
    float g = g_gate[row];
    float4* dst = (float4*)(out + ((size_t)b*TT + t) * DD);
    const float4* src = (const float4*)(g_h + (size_t)row * DD);
    float4 v = src[threadIdx.x];
    float4 d = dst[threadIdx.x];
    d.x += v.x * g; d.y += v.y * g; d.z += v.z * g; d.w += v.w * g;
    dst[threadIdx.x] = d;
}

__global__ void tail_kernel(float* __restrict__ out) {
    int i = blockIdx.x * 256 + threadIdx.x;
    size_t base = (size_t)BB * TT * DD;
    if (i < BB*KK) out[base + i] = (float)g_idx[i];
    if (i < BB*TT) out[base + BB*KK + i] = g_logits[i];
}

// ---------------- layernorm ----------------
__global__ void ln_kernel(const float* __restrict__ in, const float* __restrict__ scale,
                          const float* __restrict__ bias, float* __restrict__ out) {
    int row = blockIdx.x, tid = threadIdx.x;
    float4 v = ((const float4*)(in + (size_t)row * DD))[tid];
    float s  = v.x + v.y + v.z + v.w;
    float sq = v.x*v.x + v.y*v.y + v.z*v.z + v.w*v.w;
#pragma unroll
    for (int o = 16; o; o >>= 1) {
        s  += __shfl_xor_sync(0xffffffffu, s, o);
        sq += __shfl_xor_sync(0xffffffffu, sq, o);
    }
    __shared__ float ss[8], sq2[8];
    if ((tid & 31) == 0) { ss[tid >> 5] = s; sq2[tid >> 5] = sq; }
    __syncthreads();
    float S = 0.f, SQ = 0.f;
#pragma unroll
    for (int i = 0; i < 8; i++) { S += ss[i]; SQ += sq2[i]; }
    float mean = S * (1.f / DD);
    float var  = SQ * (1.f / DD) - mean * mean;
    float inv  = rsqrtf(var + 1e-5f);
    float4 sc = ((const float4*)scale)[tid];
    float4 bi = ((const float4*)bias)[tid];
    float4 o;
    o.x = (v.x - mean) * inv * sc.x + bi.x;
    o.y = (v.y - mean) * inv * sc.y + bi.y;
    o.z = (v.z - mean) * inv * sc.z + bi.z;
    o.w = (v.w - mean) * inv * sc.w + bi.w;
    ((float4*)(out + (size_t)row * DD))[tid] = o;
}

// ---------------- SGEMM: C = A(MxKd) @ W(KdxN) + bias, epilogue variants ----------------
__device__ __forceinline__ float gelu_f(float x) {
    float x3 = x * x * x;
    float t = tanhf(0.7978845608028654f * (x + 0.044715f * x3));
    return 0.5f * x * (1.f + t);
}

// EPI: 0 = plain, 1 = gelu, 2 = residual add (C = res + A@W + bias)
template <int EPI>
__global__ __launch_bounds__(256) void sgemm_kernel(
    const float* __restrict__ A, const float* __restrict__ W,
    const float* __restrict__ bias, const float* __restrict__ res,
    float* __restrict__ C, int M, int N, int Kd)
{
    const int ASW = 132;  // padded stride for A tile (transposed)
    __shared__ float As[16 * ASW];
    __shared__ float Bs[16 * 128];
    int bn = blockIdx.x, bm = blockIdx.y;
    int tid = threadIdx.x;
    int tx = tid & 15, ty = tid >> 4;

    float acc[8][8];
#pragma unroll
    for (int i = 0; i < 8; i++)
#pragma unroll
        for (int j = 0; j < 8; j++) acc[i][j] = 0.f;

    for (int kt = 0; kt < Kd; kt += 16) {
#pragma unroll
        for (int i = 0; i < 2; i++) {
            int id = tid * 2 + i;
            int ar = id >> 2, ac = (id & 3) << 2;
            float4 av = *(const float4*)(A + (size_t)(bm*128 + ar) * Kd + kt + ac);
            As[(ac+0)*ASW + ar] = av.x;
            As[(ac+1)*ASW + ar] = av.y;
            As[(ac+2)*ASW + ar] = av.z;
            As[(ac+3)*ASW + ar] = av.w;
            int br = id >> 5, bc = (id & 31) << 2;
            *(float4*)&Bs[br*128 + bc] = *(const float4*)(W + (size_t)(kt + br) * N + bn*128 + bc);
        }
        __syncthreads();
#pragma unroll
        for (int k = 0; k < 16; k++) {
            float ra[8], rb[8];
            *(float4*)(ra)     = *(float4*)&As[k*ASW + ty*4];
            *(float4*)(ra + 4) = *(float4*)&As[k*ASW + 64 + ty*4];
            *(float4*)(rb)     = *(float4*)&Bs[k*128 + tx*4];
            *(float4*)(rb + 4) = *(float4*)&Bs[k*128 + 64 + tx*4];
#pragma unroll
            for (int i = 0; i < 8; i++)
#pragma unroll
                for (int j = 0; j < 8; j++) acc[i][j] += ra[i] * rb[j];
        }
        __syncthreads();
    }

#pragma unroll
    for (int i = 0; i < 8; i++) {
        int ri = (i < 4) ? (ty*4 + i) : (64 + ty*4 + i - 4);
        size_t r = (size_t)bm*128 + ri;
#pragma unroll
        for (int jh = 0; jh < 2; jh++) {
            int cj = (jh == 0) ? (tx*4) : (64 + tx*4);
            int c = bn*128 + cj;
            float4 bv = *(const float4*)(bias + c);
            float o0 = acc[i][jh*4+0] + bv.x;
            float o1 = acc[i][jh*4+1] + bv.y;
            float o2 = acc[i][jh*4+2] + bv.z;
            float o3 = acc[i][jh*4+3] + bv.w;
            if (EPI == 1) { o0 = gelu_f(o0); o1 = gelu_f(o1); o2 = gelu_f(o2); o3 = gelu_f(o3); }
            if (EPI == 2) {
                float4 rv = *(const float4*)(res + r * N + c);
                o0 += rv.x; o1 += rv.y; o2 += rv.z; o3 += rv.w;
            }
            float4 ov; ov.x = o0; ov.y = o1; ov.z = o2; ov.w = o3;
            *(float4*)(C + r * N + c) = ov;
        }
    }
}

// ---------------- flash attention (fp32, causal, 64x64 tiles) ----------------
#define ATTN_SMEM_BYTES ((4096 + 3*64*68) * 4)

__global__ __launch_bounds__(256) void attn_kernel() {
    extern __shared__ float sm[];
    float* Qs = sm;                // [64][64]  (d-major: Qs[d*64 + q])
    float* Ks = Qs + 4096;         // [64][68]  (Ks[d*68 + k])
    float* Vs = Ks + 64*68;        // [64][68]  (Vs[k*68 + d])
    float* Ps = Vs + 64*68;        // [64][68]  (Ps[q*68 + k])
    __shared__ float m_s[64], l_s[64], corr_s[64];

    int tid = threadIdx.x;
    int tx = tid & 15, ty = tid >> 4;
    int qb = blockIdx.x;
    int bh = blockIdx.y;
    int b = bh >> 4, h = bh & 15;
    const float* qkv = g_qkv + (size_t)b * KK * 3 * DD + h * DHD;  // row stride 3*DD

    if (tid < 64) { m_s[tid] = -3.0e38f; l_s[tid] = 0.f; }

#pragma unroll
    for (int it = 0; it < 4; it++) {
        int id = tid + it * 256;
        int r = id >> 4; int dv = (id & 15) << 2;
        float4 v = *(const float4*)(qkv + (size_t)(qb*64 + r) * (3*DD) + dv);
        Qs[(dv+0)*64 + r] = v.x; Qs[(dv+1)*64 + r] = v.y;
        Qs[(dv+2)*64 + r] = v.z; Qs[(dv+3)*64 + r] = v.w;
    }

    float accO[4][4];
#pragma unroll
    for (int i = 0; i < 4; i++)
#pragma unroll
        for (int j = 0; j < 4; j++) accO[i][j] = 0.f;

    for (int jt = 0; jt <= qb; jt++) {
        __syncthreads();
#pragma unroll
        for (int it = 0; it < 4; it++) {
            int id = tid + it * 256;
            int r = id >> 4; int dv = (id & 15) << 2;
            float4 kv = *(const float4*)(qkv + (size_t)(jt*64 + r) * (3*DD) + DD + dv);
            Ks[(dv+0)*68 + r] = kv.x; Ks[(dv+1)*68 + r] = kv.y;
            Ks[(dv+2)*68 + r] = kv.z; Ks[(dv+3)*68 + r] = kv.w;
            *(float4*)&Vs[r*68 + dv] =
                *(const float4*)(qkv + (size_t)(jt*64 + r) * (3*DD) + 2*DD + dv);
        }
        __syncthreads();

        float sacc[4][4];
#pragma unroll
        for (int i = 0; i < 4; i++)
#pragma unroll
            for (int j = 0; j < 4; j++) sacc[i][j] = 0.f;
#pragma unroll 8
        for (int kk = 0; kk < 64; kk++) {
            float qa[4], ka[4];
            *(float4*)qa = *(float4*)&Qs[kk*64 + ty*4];
            *(float4*)ka = *(float4*)&Ks[kk*68 + tx*4];
#pragma unroll
            for (int i = 0; i < 4; i++)
#pragma unroll
                for (int j = 0; j < 4; j++) sacc[i][j] += qa[i] * ka[j];
        }
        bool diag = (jt == qb);
#pragma unroll
        for (int i = 0; i < 4; i++) {
            int gq = qb*64 + ty*4 + i;
#pragma unroll
            for (int j = 0; j < 4; j++) {
                int gk = jt*64 + tx*4 + j;
                float s = sacc[i][j] * 0.125f;
                if (diag && gk > gq) s = -3.0e38f;
                sacc[i][j] = s;
            }
        }
#pragma unroll
        for (int i = 0; i < 4; i++) {
            float rm = fmaxf(fmaxf(sacc[i][0], sacc[i][1]), fmaxf(sacc[i][2], sacc[i][3]));
#pragma unroll
            for (int o = 8; o; o >>= 1) rm = fmaxf(rm, __shfl_xor_sync(0xffffffffu, rm, o));
            if (tx == 0) {
                int r = ty*4 + i;
                float mo = m_s[r];
                float mn = fmaxf(mo, rm);
                m_s[r] = mn;
                corr_s[r] = __expf(mo - mn);
            }
        }
        __syncthreads();
#pragma unroll
        for (int i = 0; i < 4; i++) {
            int r = ty*4 + i;
            float mn = m_s[r];
            float rs = 0.f;
#pragma unroll
            for (int j = 0; j < 4; j++) {
                float p = __expf(sacc[i][j] - mn);
                rs += p;
                Ps[r*68 + tx*4 + j] = p;
            }
#pragma unroll
            for (int o = 8; o; o >>= 1) rs += __shfl_xor_sync(0xffffffffu, rs, o);
            if (tx == 0) l_s[r] = l_s[r] * corr_s[r] + rs;
        }
        __syncthreads();
        float cr[4];
#pragma unroll
        for (int i = 0; i < 4; i++) cr[i] = corr_s[ty*4 + i];
#pragma unroll
        for (int i = 0; i < 4; i++)
#pragma unroll
            for (int j = 0; j < 4; j++) accO[i][j] *= cr[i];
#pragma unroll 8
        for (int c = 0; c < 64; c++) {
            float pa[4], va[4];
            pa[0] = Ps[(ty*4+0)*68 + c];
            pa[1] = Ps[(ty*4+1)*68 + c];
            pa[2] = Ps[(ty*4+2)*68 + c];
            pa[3] = Ps[(ty*4+3)*68 + c];
            *(float4*)va = *(float4*)&Vs[c*68 + tx*4];
#pragma unroll
            for (int i = 0; i < 4; i++)
#pragma unroll
                for (int j = 0; j < 4; j++) accO[i][j] += pa[i] * va[j];
        }
    }

    float li[4];
#pragma unroll
    for (int i = 0; i < 4; i++) li[i] = 1.f / l_s[ty*4 + i];
    float* op = g_attn + (size_t)b * KK * DD + h * DHD;
#pragma unroll
    for (int i = 0; i < 4; i++) {
        int q = qb*64 + ty*4 + i;
        float4 v;
        v.x = accO[i][0] * li[i]; v.y = accO[i][1] * li[i];
        v.z = accO[i][2] * li[i]; v.w = accO[i][3] * li[i];
        *(float4*)&op[(size_t)q * DD + tx*4] = v;
    }
}

// ---------------- launch ----------------
extern "C" void kernel_launch(void* const* d_in, const int* in_sizes, int n_in,
                              void* d_out, int out_size) {
    const float* x        = (const float*)d_in[0];
    const float* w_router = (const float*)d_in[1];
    const float* b_router = (const float*)d_in[2];
    const float* ln1_s    = (const float*)d_in[3];
    const float* ln1_b    = (const float*)d_in[4];
    const float* w_qkv    = (const float*)d_in[5];
    const float* b_qkv    = (const float*)d_in[6];
    const float* w_o      = (const float*)d_in[7];
    const float* b_o      = (const float*)d_in[8];
    const float* ln2_s    = (const float*)d_in[9];
    const float* ln2_b    = (const float*)d_in[10];
    const float* w1       = (const float*)d_in[11];
    const float* b1       = (const float*)d_in[12];
    const float* w2       = (const float*)d_in[13];
    const float* b2       = (const float*)d_in[14];
    float* out = (float*)d_out;

    float *p_h, *p_a, *p_qkv, *p_attn, *p_ffn;
    cudaGetSymbolAddress((void**)&p_h,    g_h);
    cudaGetSymbolAddress((void**)&p_a,    g_a);
    cudaGetSymbolAddress((void**)&p_qkv,  g_qkv);
    cudaGetSymbolAddress((void**)&p_attn, g_attn);
    cudaGetSymbolAddress((void**)&p_ffn,  g_ffn);

    cudaFuncSetAttribute(attn_kernel, cudaFuncAttributeMaxDynamicSharedMemorySize,
                         ATTN_SMEM_BYTES);

    router_kernel<<<BB*TT/8, 256>>>(x, w_router, b_router);
    topk_kernel<<<BB, 1024>>>();
    gather_kernel<<<BB*KK, 256>>>(x);

    for (int l = 0; l < LL; l++) {
        ln_kernel<<<MROWS, 256>>>(p_h, ln1_s + l*DD, ln1_b + l*DD, p_a);
        sgemm_kernel<0><<<dim3(3*DD/128, MROWS/128), 256>>>(
            p_a, w_qkv + (size_t)l*DD*3*DD, b_qkv + (size_t)l*3*DD, nullptr, p_qkv,
            MROWS, 3*DD, DD);
        attn_kernel<<<dim3(KK/64, BB*HH), 256, ATTN_SMEM_BYTES>>>();
        sgemm_kernel<2><<<dim3(DD/128, MROWS/128), 256>>>(
            p_attn, w_o + (size_t)l*DD*DD, b_o + (size_t)l*DD, p_h, p_h,
            MROWS, DD, DD);
        ln_kernel<<<MROWS, 256>>>(p_h, ln2_s + l*DD, ln2_b + l*DD, p_a);
        sgemm_kernel<1><<<dim3(FF/128, MROWS/128), 256>>>(
            p_a, w1 + (size_t)l*DD*FF, b1 + (size_t)l*FF, nullptr, p_ffn,
            MROWS, FF, DD);
        sgemm_kernel<2><<<dim3(DD/128, MROWS/128), 256>>>(
            p_ffn, w2 + (size_t)l*FF*DD, b2 + (size_t)l*DD, p_h, p_h,
            MROWS, DD, FF);
    }

    copy_out_kernel<<<(BB*TT*DD/4)/256, 256>>>(x, out);
    scatter_kernel<<<BB*KK, 256>>>(out);

    long long full = (long long)BB*TT*DD + (long long)BB*KK + (long long)BB*TT;
    if ((long long)out_size >= full) tail_kernel<<<32, 256>>>(out);
}

// round 3
// speedup vs baseline: 2.2036x; 2.2036x over previous
#include <cuda_runtime.h>
#include <math.h>
#include <stdint.h>

#define BB 2
#define TT 4096
#define DD 1024
#define LL 2
#define HH 16
#define FF 4096
#define KK 2048
#define DHD 64
#define MROWS (BB*KK)   // 4096 (batch folded into M)

// ---------------- scratch (static device globals; no allocations) ----------------
__device__ float g_logits[BB*TT];
__device__ int   g_idx[BB*KK];
__device__ float g_gate[BB*KK];
__device__ float g_h[BB*KK*DD];
__device__ float g_a[BB*KK*DD];
__device__ float g_qkv[BB*KK*3*DD];
__device__ float g_attn[BB*KK*DD];
__device__ float g_ffn[(size_t)BB*KK*FF];

// tf32-rounded weights (same [K,N] layout as inputs)
#define WT_QKV 0
#define WT_O   (LL*DD*3*DD)
#define WT_W1  (WT_O + LL*DD*DD)
#define WT_W2  (WT_W1 + LL*DD*FF)
#define WT_TOT (WT_W2 + LL*FF*DD)
__device__ float g_wt[WT_TOT];

// ---------------- helpers ----------------
__device__ __forceinline__ uint32_t smem_u32(const void* p) {
    uint32_t a;
    asm("{ .reg .u64 t; cvta.to.shared.u64 t, %1; cvt.u32.u64 %0, t; }" : "=r"(a) : "l"(p));
    return a;
}
__device__ __forceinline__ float tf32rn(float x) {
    uint32_t u;
    asm("cvt.rna.tf32.f32 %0, %1;" : "=r"(u) : "f"(x));
    return __uint_as_float(u);
}
__device__ __forceinline__ void cpasync16(uint32_t dst, const void* src) {
    asm volatile("cp.async.cg.shared.global [%0], [%1], 16;" :: "r"(dst), "l"(src) : "memory");
}
__device__ __forceinline__ void cp_commit() {
    asm volatile("cp.async.commit_group;" ::: "memory");
}
__device__ __forceinline__ void mma8(float* d, const float* a, const float* b) {
    asm volatile("mma.sync.aligned.m16n8k8.row.col.f32.tf32.tf32.f32 "
        "{%0,%1,%2,%3}, {%4,%5,%6,%7}, {%8,%9}, {%0,%1,%2,%3};"
        : "+f"(d[0]), "+f"(d[1]), "+f"(d[2]), "+f"(d[3])
        : "r"(__float_as_uint(a[0])), "r"(__float_as_uint(a[1])),
          "r"(__float_as_uint(a[2])), "r"(__float_as_uint(a[3])),
          "r"(__float_as_uint(b[0])), "r"(__float_as_uint(b[1])));
}

__device__ __forceinline__ float gelu_f(float x) {
    float x3 = x * x * x;
    float t = tanhf(0.7978845608028654f * (x + 0.044715f * x3));
    return 0.5f * x * (1.f + t);
}

// ---------------- mma.sync tf32 GEMM: C = A(M x Kd) @ W(Kd x Ntot) + bias ----------------
// CTA tile 128x256, BK=32, double-buffered cp.async, 8 warps (warp tile 64x64)
#define MT 128
#define NT 256
#define KCH 32
#define AST 36     // A smem row stride (floats): bank = 4g+tig, conflict-free
#define BST 264    // B smem row stride (floats): bank = 8tig+g, conflict-free
#define AS_FLOATS (MT*AST)
#define BS_FLOATS (KCH*BST)
#define GEMM_SMEM ((2*AS_FLOATS + 2*BS_FLOATS)*4)

// EPI: 0 = bias only, 1 = bias+gelu+tf32 round, 2 = bias+residual add
template <int EPI>
__global__ __launch_bounds__(256, 1) void mma_gemm(
    const float* __restrict__ A, const float* __restrict__ W,
    const float* __restrict__ bias, const float* __restrict__ res,
    float* __restrict__ C, int Kd, int Ntot)
{
    extern __shared__ __align__(16) float sm[];
    float* AsBase = sm;                      // 2 stages
    float* BsBase = sm + 2*AS_FLOATS;        // 2 stages
    uint32_t as_addr = smem_u32(AsBase);
    uint32_t bs_addr = smem_u32(BsBase);

    int tid = threadIdx.x;
    int bn = blockIdx.x, bm = blockIdx.y;
    int wid = tid >> 5, lane = tid & 31;
    int wm = wid & 1, wn = wid >> 1;         // warp tile: 64 (M) x 64 (N)
    int g = lane >> 2, tig = lane & 3;

    const float* Ag = A + (size_t)(bm*MT) * Kd;
    const float* Wg = W + (size_t)bn * NT;

    float acc[4][8][4];
#pragma unroll
    for (int mi = 0; mi < 4; mi++)
#pragma unroll
        for (int ni = 0; ni < 8; ni++)
#pragma unroll
            for (int c = 0; c < 4; c++) acc[mi][ni][c] = 0.f;

    int nk = Kd / KCH;

    // stage loader: A tile 128x32 (1024 16B chunks), B tile 32x256 (2048 chunks)
    auto load_stage = [&](int s, int kt) {
#pragma unroll
        for (int i = 0; i < 4; i++) {
            int chunk = tid + 256*i;
            int row = chunk >> 3, cseg = chunk & 7;
            cpasync16(as_addr + (uint32_t)(s*AS_FLOATS + row*AST)*4 + cseg*16,
                      Ag + (size_t)row*Kd + kt*KCH + cseg*4);
        }
#pragma unroll
        for (int i = 0; i < 8; i++) {
            int chunk = tid + 256*i;
            int row = chunk >> 6, cseg = chunk & 63;
            cpasync16(bs_addr + (uint32_t)(s*BS_FLOATS + row*BST)*4 + cseg*16,
                      Wg + (size_t)(kt*KCH + row)*Ntot + cseg*4);
        }
        cp_commit();
    };

    load_stage(0, 0);

    for (int kt = 0; kt < nk; kt++) {
        if (kt + 1 < nk) load_stage((kt+1) & 1, kt+1);
        if (kt + 1 < nk) asm volatile("cp.async.wait_group 1;" ::: "memory");
        else             asm volatile("cp.async.wait_group 0;" ::: "memory");
        __syncthreads();

        const float* as = AsBase + (kt & 1)*AS_FLOATS;
        const float* bs = BsBase + (kt & 1)*BS_FLOATS;
#pragma unroll
        for (int ks = 0; ks < 4; ks++) {
            int k = ks*8;
            float af[4][4];
#pragma unroll
            for (int mi = 0; mi < 4; mi++) {
                int r = wm*64 + mi*16;
                af[mi][0] = as[(r+g)*AST + k + tig];
                af[mi][1] = as[(r+g+8)*AST + k + tig];
                af[mi][2] = as[(r+g)*AST + k + tig + 4];
                af[mi][3] = as[(r+g+8)*AST + k + tig + 4];
            }
            float bf[8][2];
#pragma unroll
            for (int ni = 0; ni < 8; ni++) {
                int c = wn*64 + ni*8 + g;
                bf[ni][0] = bs[(k+tig)*BST + c];
                bf[ni][1] = bs[(k+tig+4)*BST + c];
            }
#pragma unroll
            for (int mi = 0; mi < 4; mi++)
#pragma unroll
                for (int ni = 0; ni < 8; ni++)
                    mma8(acc[mi][ni], af[mi], bf[ni]);
        }
        __syncthreads();
    }

    // ---- epilogue ----
#pragma unroll
    for (int mi = 0; mi < 4; mi++) {
        int r0 = bm*MT + wm*64 + mi*16 + g;
#pragma unroll
        for (int ni = 0; ni < 8; ni++) {
            int col = bn*NT + wn*64 + ni*8 + tig*2;
            float2 bv = *(const float2*)(bias + col);
#pragma unroll
            for (int hrow = 0; hrow < 2; hrow++) {
                int r = r0 + hrow*8;
                float o0 = acc[mi][ni][hrow*2+0] + bv.x;
                float o1 = acc[mi][ni][hrow*2+1] + bv.y;
                if (EPI == 1) { o0 = tf32rn(gelu_f(o0)); o1 = tf32rn(gelu_f(o1)); }
                if (EPI == 2) {
                    float2 rv = *(const float2*)(res + (size_t)r * Ntot + col);
                    o0 += rv.x; o1 += rv.y;
                }
                float2 ov; ov.x = o0; ov.y = o1;
                *(float2*)(C + (size_t)r * Ntot + col) = ov;
            }
        }
    }
}

// ---------------- weight rounding (fp32 -> tf32-RNA, same layout) ----------------
__global__ void round_kernel(const float* __restrict__ src, float* __restrict__ dst, int n4) {
    int i = blockIdx.x * 256 + threadIdx.x;
    if (i < n4) {
        float4 v = ((const float4*)src)[i];
        v.x = tf32rn(v.x); v.y = tf32rn(v.y); v.z = tf32rn(v.z); v.w = tf32rn(v.w);
        ((float4*)dst)[i] = v;
    }
}

// ---------------- router ----------------
__global__ void router_kernel(const float* __restrict__ x,
                              const float* __restrict__ w,
                              const float* __restrict__ br) {
    int row  = blockIdx.x * 8 + (threadIdx.x >> 5);
    int lane = threadIdx.x & 31;
    const float4* xr = (const float4*)(x + (size_t)row * DD);
    const float4* wr = (const float4*)w;
    float s = 0.f;
#pragma unroll
    for (int i = 0; i < 8; i++) {
        int c = lane + i * 32;
        float4 a = xr[c], b = wr[c];
        s += a.x*b.x + a.y*b.y + a.z*b.z + a.w*b.w;
    }
#pragma unroll
    for (int o = 16; o; o >>= 1) s += __shfl_xor_sync(0xffffffffu, s, o);
    if (!lane) g_logits[row] = s + br[0];
}

// ---------------- exact top-K via radix select + scan ----------------
__global__ void topk_kernel() {
    __shared__ unsigned key[TT];
    __shared__ int s_cnt;
    __shared__ int s_scan[1024];
    int b = blockIdx.x, tid = threadIdx.x;

    for (int t = tid; t < TT; t += 1024) {
        unsigned u = __float_as_uint(g_logits[b*TT + t]);
        u = (u & 0x80000000u) ? ~u : (u | 0x80000000u);
        key[t] = u;
    }
    __syncthreads();

    unsigned prefix = 0; int needed = KK;
    for (int bit = 31; bit >= 0; --bit) {
        if (!tid) s_cnt = 0;
        __syncthreads();
        unsigned cand = prefix | (1u << bit);
        unsigned mask = ~((1u << bit) - 1u);
        int loc = 0;
        for (int t = tid; t < TT; t += 1024) loc += ((key[t] & mask) == cand);
#pragma unroll
        for (int o = 16; o; o >>= 1) loc += __shfl_xor_sync(0xffffffffu, loc, o);
        if ((tid & 31) == 0) atomicAdd(&s_cnt, loc);
        __syncthreads();
        int c = s_cnt;
        if (needed <= c) prefix = cand; else needed -= c;
        __syncthreads();
    }
    int base = tid * 4;
    int vals[4]; int run = 0;
#pragma unroll
    for (int i = 0; i < 4; i++) {
        unsigned k2 = key[base + i];
        int gt = (k2 > prefix), eq = (k2 == prefix);
        vals[i] = run;
        run += (gt << 16) | eq;
    }
    s_scan[tid] = run;
    __syncthreads();
    for (int off = 1; off < 1024; off <<= 1) {
        int v = (tid >= off) ? s_scan[tid - off] : 0;
        __syncthreads();
        s_scan[tid] += v;
        __syncthreads();
    }
    int excl = tid ? s_scan[tid - 1] : 0;
#pragma unroll
    for (int i = 0; i < 4; i++) {
        int t = base + i;
        unsigned k2 = key[t];
        int pre = excl + vals[i];
        int gtB = pre >> 16, eqB = pre & 0xFFFF;
        bool sel = (k2 > prefix) || (k2 == prefix && eqB < needed);
        if (sel) {
            int pos = gtB + min(eqB, needed);
            g_idx[b*KK + pos] = t;
            float lg = g_logits[b*TT + t];
            g_gate[b*KK + pos] = 1.f / (1.f + expf(-lg));
        }
    }
}

// ---------------- gather / scatter / output ----------------
__global__ void gather_kernel(const float* __restrict__ x) {
    int row = blockIdx.x;
    int b = row / KK;
    int t = g_idx[row];
    const float4* src = (const float4*)(x + ((size_t)b*TT + t) * DD);
    float4* dst = (float4*)(g_h + (size_t)row * DD);
    dst[threadIdx.x] = src[threadIdx.x];
}

__global__ void copy_out_kernel(const float* __restrict__ x, float* __restrict__ out) {
    size_t i = (size_t)blockIdx.x * 256 + threadIdx.x;
    ((float4*)out)[i] = ((const float4*)x)[i];
}

__global__ void scatter_kernel(float* __restrict__ out) {
    int row = blockIdx.x;
    int b = row / KK;
    int t = g_idx[row];
    float g = g_gate[row];
    float4* dst = (float4*)(out + ((size_t)b*TT + t) * DD);
    const float4* src = (const float4*)(g_h + (size_t)row * DD);
    float4 v = src[threadIdx.x];
    float4 d = dst[threadIdx.x];
    d.x += v.x * g; d.y += v.y * g; d.z += v.z * g; d.w += v.w * g;
    dst[threadIdx.x] = d;
}

__global__ void tail_kernel(float* __restrict__ out) {
    int i = blockIdx.x * 256 + threadIdx.x;
    size_t base = (size_t)BB * TT * DD;
    if (i < BB*KK) out[base + i] = (float)g_idx[i];
    if (i < BB*TT) out[base + BB*KK + i] = g_logits[i];
}

// ---------------- layernorm (output tf32-rounded: feeds GEMM A) ----------------
__global__ void ln_kernel(const float* __restrict__ in, const float* __restrict__ scale,
                          const float* __restrict__ bias, float* __restrict__ out) {
    int row = blockIdx.x, tid = threadIdx.x;
    float4 v = ((const float4*)(in + (size_t)row * DD))[tid];
    float s  = v.x + v.y + v.z + v.w;
    float sq = v.x*v.x + v.y*v.y + v.z*v.z + v.w*v.w;
#pragma unroll
    for (int o = 16; o; o >>= 1) {
        s  += __shfl_xor_sync(0xffffffffu, s, o);
        sq += __shfl_xor_sync(0xffffffffu, sq, o);
    }
    __shared__ float ss[8], sq2[8];
    if ((tid & 31) == 0) { ss[tid >> 5] = s; sq2[tid >> 5] = sq; }
    __syncthreads();
    float S = 0.f, SQ = 0.f;
#pragma unroll
    for (int i = 0; i < 8; i++) { S += ss[i]; SQ += sq2[i]; }
    float mean = S * (1.f / DD);
    float var  = SQ * (1.f / DD) - mean * mean;
    float inv  = rsqrtf(var + 1e-5f);
    float4 sc = ((const float4*)scale)[tid];
    float4 bi = ((const float4*)bias)[tid];
    float4 o;
    o.x = tf32rn((v.x - mean) * inv * sc.x + bi.x);
    o.y = tf32rn((v.y - mean) * inv * sc.y + bi.y);
    o.z = tf32rn((v.z - mean) * inv * sc.z + bi.z);
    o.w = tf32rn((v.w - mean) * inv * sc.w + bi.w);
    ((float4*)(out + (size_t)row * DD))[tid] = o;
}

// ---------------- flash attention (fp32, causal, 64x64 tiles) ----------------
#define ATTN_SMEM_BYTES ((4096 + 3*64*68) * 4)

__global__ __launch_bounds__(256) void attn_kernel() {
    extern __shared__ float smA[];
    float* Qs = smA;
    float* Ks = Qs + 4096;
    float* Vs = Ks + 64*68;
    float* Ps = Vs + 64*68;
    __shared__ float m_s[64], l_s[64], corr_s[64];

    int tid = threadIdx.x;
    int tx = tid & 15, ty = tid >> 4;
    int qb = blockIdx.x;
    int bh = blockIdx.y;
    int b = bh >> 4, h = bh & 15;
    const float* qkv = g_qkv + (size_t)b * KK * 3 * DD + h * DHD;

    if (tid < 64) { m_s[tid] = -3.0e38f; l_s[tid] = 0.f; }

#pragma unroll
    for (int it = 0; it < 4; it++) {
        int id = tid + it * 256;
        int r = id >> 4; int dv = (id & 15) << 2;
        float4 v = *(const float4*)(qkv + (size_t)(qb*64 + r) * (3*DD) + dv);
        Qs[(dv+0)*64 + r] = v.x; Qs[(dv+1)*64 + r] = v.y;
        Qs[(dv+2)*64 + r] = v.z; Qs[(dv+3)*64 + r] = v.w;
    }

    float accO[4][4];
#pragma unroll
    for (int i = 0; i < 4; i++)
#pragma unroll
        for (int j = 0; j < 4; j++) accO[i][j] = 0.f;

    for (int jt = 0; jt <= qb; jt++) {
        __syncthreads();
#pragma unroll
        for (int it = 0; it < 4; it++) {
            int id = tid + it * 256;
            int r = id >> 4; int dv = (id & 15) << 2;
            float4 kv = *(const float4*)(qkv + (size_t)(jt*64 + r) * (3*DD) + DD + dv);
            Ks[(dv+0)*68 + r] = kv.x; Ks[(dv+1)*68 + r] = kv.y;
            Ks[(dv+2)*68 + r] = kv.z; Ks[(dv+3)*68 + r] = kv.w;
            *(float4*)&Vs[r*68 + dv] =
                *(const float4*)(qkv + (size_t)(jt*64 + r) * (3*DD) + 2*DD + dv);
        }
        __syncthreads();

        float sacc[4][4];
#pragma unroll
        for (int i = 0; i < 4; i++)
#pragma unroll
            for (int j = 0; j < 4; j++) sacc[i][j] = 0.f;
#pragma unroll 8
        for (int kk = 0; kk < 64; kk++) {
            float qa[4], ka[4];
            *(float4*)qa = *(float4*)&Qs[kk*64 + ty*4];
            *(float4*)ka = *(float4*)&Ks[kk*68 + tx*4];
#pragma unroll
            for (int i = 0; i < 4; i++)
#pragma unroll
                for (int j = 0; j < 4; j++) sacc[i][j] += qa[i] * ka[j];
        }
        bool diag = (jt == qb);
#pragma unroll
        for (int i = 0; i < 4; i++) {
            int gq = qb*64 + ty*4 + i;
#pragma unroll
            for (int j = 0; j < 4; j++) {
                int gk = jt*64 + tx*4 + j;
                float s = sacc[i][j] * 0.125f;
                if (diag && gk > gq) s = -3.0e38f;
                sacc[i][j] = s;
            }
        }
#pragma unroll
        for (int i = 0; i < 4; i++) {
            float rm = fmaxf(fmaxf(sacc[i][0], sacc[i][1]), fmaxf(sacc[i][2], sacc[i][3]));
#pragma unroll
            for (int o = 8; o; o >>= 1) rm = fmaxf(rm, __shfl_xor_sync(0xffffffffu, rm, o));
            if (tx == 0) {
                int r = ty*4 + i;
                float mo = m_s[r];
                float mn = fmaxf(mo, rm);
                m_s[r] = mn;
                corr_s[r] = __expf(mo - mn);
            }
        }
        __syncthreads();
#pragma unroll
        for (int i = 0; i < 4; i++) {
            int r = ty*4 + i;
            float mn = m_s[r];
            float rs = 0.f;
#pragma unroll
            for (int j = 0; j < 4; j++) {
                float p = __expf(sacc[i][j] - mn);
                rs += p;
                Ps[r*68 + tx*4 + j] = p;
            }
#pragma unroll
            for (int o = 8; o; o >>= 1) rs += __shfl_xor_sync(0xffffffffu, rs, o);
            if (tx == 0) l_s[r] = l_s[r] * corr_s[r] + rs;
        }
        __syncthreads();
        float cr[4];
#pragma unroll
        for (int i = 0; i < 4; i++) cr[i] = corr_s[ty*4 + i];
#pragma unroll
        for (int i = 0; i < 4; i++)
#pragma unroll
            for (int j = 0; j < 4; j++) accO[i][j] *= cr[i];
#pragma unroll 8
        for (int c = 0; c < 64; c++) {
            float pa[4], va[4];
            pa[0] = Ps[(ty*4+0)*68 + c];
            pa[1] = Ps[(ty*4+1)*68 + c];
            pa[2] = Ps[(ty*4+2)*68 + c];
            pa[3] = Ps[(ty*4+3)*68 + c];
            *(float4*)va = *(float4*)&Vs[c*68 + tx*4];
#pragma unroll
            for (int i = 0; i < 4; i++)
#pragma unroll
                for (int j = 0; j < 4; j++) accO[i][j] += pa[i] * va[j];
        }
    }

    float li[4];
#pragma unroll
    for (int i = 0; i < 4; i++) li[i] = 1.f / l_s[ty*4 + i];
    float* op = g_attn + (size_t)b * KK * DD + h * DHD;
#pragma unroll
    for (int i = 0; i < 4; i++) {
        int q = qb*64 + ty*4 + i;
        float4 v;
        v.x = tf32rn(accO[i][0] * li[i]); v.y = tf32rn(accO[i][1] * li[i]);
        v.z = tf32rn(accO[i][2] * li[i]); v.w = tf32rn(accO[i][3] * li[i]);
        *(float4*)&op[(size_t)q * DD + tx*4] = v;
    }
}

// ---------------- launch ----------------
extern "C" void kernel_launch(void* const* d_in, const int* in_sizes, int n_in,
                              void* d_out, int out_size) {
    const float* x        = (const float*)d_in[0];
    const float* w_router = (const float*)d_in[1];
    const float* b_router = (const float*)d_in[2];
    const float* ln1_s    = (const float*)d_in[3];
    const float* ln1_b    = (const float*)d_in[4];
    const float* w_qkv    = (const float*)d_in[5];
    const float* b_qkv    = (const float*)d_in[6];
    const float* w_o      = (const float*)d_in[7];
    const float* b_o      = (const float*)d_in[8];
    const float* ln2_s    = (const float*)d_in[9];
    const float* ln2_b    = (const float*)d_in[10];
    const float* w1       = (const float*)d_in[11];
    const float* b1       = (const float*)d_in[12];
    const float* w2       = (const float*)d_in[13];
    const float* b2       = (const float*)d_in[14];
    float* out = (float*)d_out;

    float *p_h, *p_a, *p_qkv, *p_attn, *p_ffn, *p_wt;
    cudaGetSymbolAddress((void**)&p_h,    g_h);
    cudaGetSymbolAddress((void**)&p_a,    g_a);
    cudaGetSymbolAddress((void**)&p_qkv,  g_qkv);
    cudaGetSymbolAddress((void**)&p_attn, g_attn);
    cudaGetSymbolAddress((void**)&p_ffn,  g_ffn);
    cudaGetSymbolAddress((void**)&p_wt,   g_wt);

    cudaFuncSetAttribute(attn_kernel, cudaFuncAttributeMaxDynamicSharedMemorySize,
                         ATTN_SMEM_BYTES);
    cudaFuncSetAttribute(mma_gemm<0>, cudaFuncAttributeMaxDynamicSharedMemorySize, GEMM_SMEM);
    cudaFuncSetAttribute(mma_gemm<1>, cudaFuncAttributeMaxDynamicSharedMemorySize, GEMM_SMEM);
    cudaFuncSetAttribute(mma_gemm<2>, cudaFuncAttributeMaxDynamicSharedMemorySize, GEMM_SMEM);

    // round all weights to tf32 (RNA) once per launch
    {
        int n;
        n = LL*DD*3*DD/4; round_kernel<<<(n+255)/256, 256>>>(w_qkv, p_wt + WT_QKV, n);
        n = LL*DD*DD/4;   round_kernel<<<(n+255)/256, 256>>>(w_o,   p_wt + WT_O,   n);
        n = LL*DD*FF/4;   round_kernel<<<(n+255)/256, 256>>>(w1,    p_wt + WT_W1,  n);
        n = LL*FF*DD/4;   round_kernel<<<(n+255)/256, 256>>>(w2,    p_wt + WT_W2,  n);
    }

    router_kernel<<<BB*TT/8, 256>>>(x, w_router, b_router);
    topk_kernel<<<BB, 1024>>>();
    gather_kernel<<<BB*KK, 256>>>(x);

    for (int l = 0; l < LL; l++) {
        ln_kernel<<<MROWS, 256>>>(p_h, ln1_s + l*DD, ln1_b + l*DD, p_a);
        mma_gemm<0><<<dim3(3*DD/NT, MROWS/MT), 256, GEMM_SMEM>>>(
            p_a, p_wt + WT_QKV + (size_t)l*3*DD*DD, b_qkv + (size_t)l*3*DD, nullptr,
            p_qkv, DD, 3*DD);
        attn_kernel<<<dim3(KK/64, BB*HH), 256, ATTN_SMEM_BYTES>>>();
        mma_gemm<2><<<dim3(DD/NT, MROWS/MT), 256, GEMM_SMEM>>>(
            p_attn, p_wt + WT_O + (size_t)l*DD*DD, b_o + (size_t)l*DD, p_h,
            p_h, DD, DD);
        ln_kernel<<<MROWS, 256>>>(p_h, ln2_s + l*DD, ln2_b + l*DD, p_a);
        mma_gemm<1><<<dim3(FF/NT, MROWS/MT), 256, GEMM_SMEM>>>(
            p_a, p_wt + WT_W1 + (size_t)l*FF*DD, b1 + (size_t)l*FF, nullptr,
            p_ffn, DD, FF);
        mma_gemm<2><<<dim3(DD/NT, MROWS/MT), 256, GEMM_SMEM>>>(
            p_ffn, p_wt + WT_W2 + (size_t)l*DD*FF, b2 + (size_t)l*DD, p_h,
            p_h, FF, DD);
    }

    copy_out_kernel<<<(BB*TT*DD/4)/256, 256>>>(x, out);
    scatter_kernel<<<BB*KK, 256>>>(out);

    long long full = (long long)BB*TT*DD + (long long)BB*KK + (long long)BB*TT;
    if ((long long)out_size >= full) tail_kernel<<<32, 256>>>(out);
}

// round 4
// speedup vs baseline: 3.3262x; 1.5095x over previous
#include <cuda_runtime.h>
#include <math.h>
#include <stdint.h>

#define BB 2
#define TT 4096
#define DD 1024
#define LL 2
#define HH 16
#define FF 4096
#define KK 2048
#define DHD 64
#define MROWS (BB*KK)   // 4096 (batch folded into M)

// ---------------- scratch (static device globals; no allocations) ----------------
__device__ float g_logits[BB*TT];
__device__ int   g_idx[BB*KK];
__device__ float g_gate[BB*KK];
__device__ float g_h[BB*KK*DD];
__device__ float g_a[BB*KK*DD];
__device__ float g_qkv[BB*KK*3*DD];
__device__ float g_attn[BB*KK*DD];
__device__ float g_ffn[(size_t)BB*KK*FF];

// tf32-rounded weights (same [K,N] layout as inputs)
#define WT_QKV 0
#define WT_O   (LL*DD*3*DD)
#define WT_W1  (WT_O + LL*DD*DD)
#define WT_W2  (WT_W1 + LL*DD*FF)
#define WT_TOT (WT_W2 + LL*FF*DD)
__device__ float g_wt[WT_TOT];

// ---------------- helpers ----------------
__device__ __forceinline__ uint32_t smem_u32(const void* p) {
    uint32_t a;
    asm("{ .reg .u64 t; cvta.to.shared.u64 t, %1; cvt.u32.u64 %0, t; }" : "=r"(a) : "l"(p));
    return a;
}
__device__ __forceinline__ float tf32rn(float x) {
    uint32_t u;
    asm("cvt.rna.tf32.f32 %0, %1;" : "=r"(u) : "f"(x));
    return __uint_as_float(u);
}
__device__ __forceinline__ void cpasync16(uint32_t dst, const void* src) {
    asm volatile("cp.async.cg.shared.global [%0], [%1], 16;" :: "r"(dst), "l"(src) : "memory");
}
__device__ __forceinline__ void cp_commit() {
    asm volatile("cp.async.commit_group;" ::: "memory");
}
__device__ __forceinline__ void mma8(float* d, const float* a, const float* b) {
    asm volatile("mma.sync.aligned.m16n8k8.row.col.f32.tf32.tf32.f32 "
        "{%0,%1,%2,%3}, {%4,%5,%6,%7}, {%8,%9}, {%0,%1,%2,%3};"
        : "+f"(d[0]), "+f"(d[1]), "+f"(d[2]), "+f"(d[3])
        : "r"(__float_as_uint(a[0])), "r"(__float_as_uint(a[1])),
          "r"(__float_as_uint(a[2])), "r"(__float_as_uint(a[3])),
          "r"(__float_as_uint(b[0])), "r"(__float_as_uint(b[1])));
}

__device__ __forceinline__ float gelu_f(float x) {
    float x3 = x * x * x;
    float t = tanhf(0.7978845608028654f * (x + 0.044715f * x3));
    return 0.5f * x * (1.f + t);
}

// ---------------- mma.sync tf32 GEMM: C = A(M x Kd) @ W(Kd x Ntot) + bias ----------------
// CTA tile 128x256, BK=32, double-buffered cp.async, 8 warps (warp tile 64x64)
#define MT 128
#define NT 256
#define KCH 32
#define AST 36     // A smem row stride (floats): conflict-free fragment loads
#define BST 264    // B smem row stride (floats): conflict-free fragment loads
#define AS_FLOATS (MT*AST)
#define BS_FLOATS (KCH*BST)
#define GEMM_SMEM ((2*AS_FLOATS + 2*BS_FLOATS)*4)

// EPI: 0 = bias, 1 = bias+gelu+tf32 round, 2 = bias+residual add, 3 = bias+tf32 round
template <int EPI>
__global__ __launch_bounds__(256, 1) void mma_gemm(
    const float* __restrict__ A, const float* __restrict__ W,
    const float* __restrict__ bias, const float* __restrict__ res,
    float* __restrict__ C, int Kd, int Ntot)
{
    extern __shared__ __align__(16) float sm[];
    float* AsBase = sm;                      // 2 stages
    float* BsBase = sm + 2*AS_FLOATS;        // 2 stages
    uint32_t as_addr = smem_u32(AsBase);
    uint32_t bs_addr = smem_u32(BsBase);

    int tid = threadIdx.x;
    int bn = blockIdx.x, bm = blockIdx.y;
    int wid = tid >> 5, lane = tid & 31;
    int wm = wid & 1, wn = wid >> 1;         // warp tile: 64 (M) x 64 (N)
    int g = lane >> 2, tig = lane & 3;

    const float* Ag = A + (size_t)(bm*MT) * Kd;
    const float* Wg = W + (size_t)bn * NT;

    float acc[4][8][4];
#pragma unroll
    for (int mi = 0; mi < 4; mi++)
#pragma unroll
        for (int ni = 0; ni < 8; ni++)
#pragma unroll
            for (int c = 0; c < 4; c++) acc[mi][ni][c] = 0.f;

    int nk = Kd / KCH;

    auto load_stage = [&](int s, int kt) {
#pragma unroll
        for (int i = 0; i < 4; i++) {
            int chunk = tid + 256*i;
            int row = chunk >> 3, cseg = chunk & 7;
            cpasync16(as_addr + (uint32_t)(s*AS_FLOATS + row*AST)*4 + cseg*16,
                      Ag + (size_t)row*Kd + kt*KCH + cseg*4);
        }
#pragma unroll
        for (int i = 0; i < 8; i++) {
            int chunk = tid + 256*i;
            int row = chunk >> 6, cseg = chunk & 63;
            cpasync16(bs_addr + (uint32_t)(s*BS_FLOATS + row*BST)*4 + cseg*16,
                      Wg + (size_t)(kt*KCH + row)*Ntot + cseg*4);
        }
        cp_commit();
    };

    load_stage(0, 0);

    for (int kt = 0; kt < nk; kt++) {
        if (kt + 1 < nk) load_stage((kt+1) & 1, kt+1);
        if (kt + 1 < nk) asm volatile("cp.async.wait_group 1;" ::: "memory");
        else             asm volatile("cp.async.wait_group 0;" ::: "memory");
        __syncthreads();

        const float* as = AsBase + (kt & 1)*AS_FLOATS;
        const float* bs = BsBase + (kt & 1)*BS_FLOATS;
#pragma unroll
        for (int ks = 0; ks < 4; ks++) {
            int k = ks*8;
            float af[4][4];
#pragma unroll
            for (int mi = 0; mi < 4; mi++) {
                int r = wm*64 + mi*16;
                af[mi][0] = as[(r+g)*AST + k + tig];
                af[mi][1] = as[(r+g+8)*AST + k + tig];
                af[mi][2] = as[(r+g)*AST + k + tig + 4];
                af[mi][3] = as[(r+g+8)*AST + k + tig + 4];
            }
            float bf[8][2];
#pragma unroll
            for (int ni = 0; ni < 8; ni++) {
                int c = wn*64 + ni*8 + g;
                bf[ni][0] = bs[(k+tig)*BST + c];
                bf[ni][1] = bs[(k+tig+4)*BST + c];
            }
#pragma unroll
            for (int mi = 0; mi < 4; mi++)
#pragma unroll
                for (int ni = 0; ni < 8; ni++)
                    mma8(acc[mi][ni], af[mi], bf[ni]);
        }
        __syncthreads();
    }

    // ---- epilogue ----
#pragma unroll
    for (int mi = 0; mi < 4; mi++) {
        int r0 = bm*MT + wm*64 + mi*16 + g;
#pragma unroll
        for (int ni = 0; ni < 8; ni++) {
            int col = bn*NT + wn*64 + ni*8 + tig*2;
            float2 bv = *(const float2*)(bias + col);
#pragma unroll
            for (int hrow = 0; hrow < 2; hrow++) {
                int r = r0 + hrow*8;
                float o0 = acc[mi][ni][hrow*2+0] + bv.x;
                float o1 = acc[mi][ni][hrow*2+1] + bv.y;
                if (EPI == 1) { o0 = tf32rn(gelu_f(o0)); o1 = tf32rn(gelu_f(o1)); }
                if (EPI == 2) {
                    float2 rv = *(const float2*)(res + (size_t)r * Ntot + col);
                    o0 += rv.x; o1 += rv.y;
                }
                if (EPI == 3) { o0 = tf32rn(o0); o1 = tf32rn(o1); }
                float2 ov; ov.x = o0; ov.y = o1;
                *(float2*)(C + (size_t)r * Ntot + col) = ov;
            }
        }
    }
}

// ---------------- weight rounding (fp32 -> tf32-RNA, same layout) ----------------
__global__ void round_kernel(const float* __restrict__ src, float* __restrict__ dst, int n4) {
    int i = blockIdx.x * 256 + threadIdx.x;
    if (i < n4) {
        float4 v = ((const float4*)src)[i];
        v.x = tf32rn(v.x); v.y = tf32rn(v.y); v.z = tf32rn(v.z); v.w = tf32rn(v.w);
        ((float4*)dst)[i] = v;
    }
}

// ---------------- router ----------------
__global__ void router_kernel(const float* __restrict__ x,
                              const float* __restrict__ w,
                              const float* __restrict__ br) {
    int row  = blockIdx.x * 8 + (threadIdx.x >> 5);
    int lane = threadIdx.x & 31;
    const float4* xr = (const float4*)(x + (size_t)row * DD);
    const float4* wr = (const float4*)w;
    float s = 0.f;
#pragma unroll
    for (int i = 0; i < 8; i++) {
        int c = lane + i * 32;
        float4 a = xr[c], b = wr[c];
        s += a.x*b.x + a.y*b.y + a.z*b.z + a.w*b.w;
    }
#pragma unroll
    for (int o = 16; o; o >>= 1) s += __shfl_xor_sync(0xffffffffu, s, o);
    if (!lane) g_logits[row] = s + br[0];
}

// ---------------- exact top-K via radix select + scan ----------------
__global__ void topk_kernel() {
    __shared__ unsigned key[TT];
    __shared__ int s_cnt;
    __shared__ int s_scan[1024];
    int b = blockIdx.x, tid = threadIdx.x;

    for (int t = tid; t < TT; t += 1024) {
        unsigned u = __float_as_uint(g_logits[b*TT + t]);
        u = (u & 0x80000000u) ? ~u : (u | 0x80000000u);
        key[t] = u;
    }
    __syncthreads();

    unsigned prefix = 0; int needed = KK;
    for (int bit = 31; bit >= 0; --bit) {
        if (!tid) s_cnt = 0;
        __syncthreads();
        unsigned cand = prefix | (1u << bit);
        unsigned mask = ~((1u << bit) - 1u);
        int loc = 0;
        for (int t = tid; t < TT; t += 1024) loc += ((key[t] & mask) == cand);
#pragma unroll
        for (int o = 16; o; o >>= 1) loc += __shfl_xor_sync(0xffffffffu, loc, o);
        if ((tid & 31) == 0) atomicAdd(&s_cnt, loc);
        __syncthreads();
        int c = s_cnt;
        if (needed <= c) prefix = cand; else needed -= c;
        __syncthreads();
    }
    int base = tid * 4;
    int vals[4]; int run = 0;
#pragma unroll
    for (int i = 0; i < 4; i++) {
        unsigned k2 = key[base + i];
        int gt = (k2 > prefix), eq = (k2 == prefix);
        vals[i] = run;
        run += (gt << 16) | eq;
    }
    s_scan[tid] = run;
    __syncthreads();
    for (int off = 1; off < 1024; off <<= 1) {
        int v = (tid >= off) ? s_scan[tid - off] : 0;
        __syncthreads();
        s_scan[tid] += v;
        __syncthreads();
    }
    int excl = tid ? s_scan[tid - 1] : 0;
#pragma unroll
    for (int i = 0; i < 4; i++) {
        int t = base + i;
        unsigned k2 = key[t];
        int pre = excl + vals[i];
        int gtB = pre >> 16, eqB = pre & 0xFFFF;
        bool sel = (k2 > prefix) || (k2 == prefix && eqB < needed);
        if (sel) {
            int pos = gtB + min(eqB, needed);
            g_idx[b*KK + pos] = t;
            float lg = g_logits[b*TT + t];
            g_gate[b*KK + pos] = 1.f / (1.f + expf(-lg));
        }
    }
}

// ---------------- gather / scatter / output ----------------
__global__ void gather_kernel(const float* __restrict__ x) {
    int row = blockIdx.x;
    int b = row / KK;
    int t = g_idx[row];
    const float4* src = (const float4*)(x + ((size_t)b*TT + t) * DD);
    float4* dst = (float4*)(g_h + (size_t)row * DD);
    dst[threadIdx.x] = src[threadIdx.x];
}

__global__ void copy_out_kernel(const float* __restrict__ x, float* __restrict__ out) {
    size_t i = (size_t)blockIdx.x * 256 + threadIdx.x;
    ((float4*)out)[i] = ((const float4*)x)[i];
}

__global__ void scatter_kernel(float* __restrict__ out) {
    int row = blockIdx.x;
    int b = row / KK;
    int t = g_idx[row];
    float g = g_gate[row];
    float4* dst = (float4*)(out + ((size_t)b*TT + t) * DD);
    const float4* src = (const float4*)(g_h + (size_t)row * DD);
    float4 v = src[threadIdx.x];
    float4 d = dst[threadIdx.x];
    d.x += v.x * g; d.y += v.y * g; d.z += v.z * g; d.w += v.w * g;
    dst[threadIdx.x] = d;
}

__global__ void tail_kernel(float* __restrict__ out) {
    int i = blockIdx.x * 256 + threadIdx.x;
    size_t base = (size_t)BB * TT * DD;
    if (i < BB*KK) out[base + i] = (float)g_idx[i];
    if (i < BB*TT) out[base + BB*KK + i] = g_logits[i];
}

// ---------------- layernorm (output tf32-rounded: feeds GEMM A) ----------------
__global__ void ln_kernel(const float* __restrict__ in, const float* __restrict__ scale,
                          const float* __restrict__ bias, float* __restrict__ out) {
    int row = blockIdx.x, tid = threadIdx.x;
    float4 v = ((const float4*)(in + (size_t)row * DD))[tid];
    float s  = v.x + v.y + v.z + v.w;
    float sq = v.x*v.x + v.y*v.y + v.z*v.z + v.w*v.w;
#pragma unroll
    for (int o = 16; o; o >>= 1) {
        s  += __shfl_xor_sync(0xffffffffu, s, o);
        sq += __shfl_xor_sync(0xffffffffu, sq, o);
    }
    __shared__ float ss[8], sq2[8];
    if ((tid & 31) == 0) { ss[tid >> 5] = s; sq2[tid >> 5] = sq; }
    __syncthreads();
    float S = 0.f, SQ = 0.f;
#pragma unroll
    for (int i = 0; i < 8; i++) { S += ss[i]; SQ += sq2[i]; }
    float mean = S * (1.f / DD);
    float var  = SQ * (1.f / DD) - mean * mean;
    float inv  = rsqrtf(var + 1e-5f);
    float4 sc = ((const float4*)scale)[tid];
    float4 bi = ((const float4*)bias)[tid];
    float4 o;
    o.x = tf32rn((v.x - mean) * inv * sc.x + bi.x);
    o.y = tf32rn((v.y - mean) * inv * sc.y + bi.y);
    o.z = tf32rn((v.z - mean) * inv * sc.z + bi.z);
    o.w = tf32rn((v.w - mean) * inv * sc.w + bi.w);
    ((float4*)(out + (size_t)row * DD))[tid] = o;
}

// ---------------- flash attention v2: mma.sync tf32, causal, 64x64 tiles ----------------
// 4 warps, each owns 16 q-rows. Strides: Q/K/P = 68 floats, V = 72 floats.
#define AQ 4352        // 64*68
#define AK 4352
#define AP 4352
#define AV 4608        // 64*72
#define ATTN2_SMEM ((AQ + 2*AK + AP + 2*AV)*4)

__global__ __launch_bounds__(128) void attn_mma_kernel() {
    extern __shared__ __align__(16) float sm[];
    float* Qs = sm;
    float* Ks = sm + AQ;                 // 2 stages
    float* Ps = sm + AQ + 2*AK;
    float* Vs = sm + AQ + 2*AK + AP;     // 2 stages
    uint32_t q_addr = smem_u32(Qs);
    uint32_t k_addr = smem_u32(Ks);
    uint32_t v_addr = smem_u32(Vs);

    int tid = threadIdx.x;
    int wid = tid >> 5, lane = tid & 31;
    int g = lane >> 2, tig = lane & 3;
    int qb = gridDim.x - 1 - blockIdx.x;      // heavy tiles first
    int bh = blockIdx.y;
    int b = bh >> 4, h = bh & 15;
    const float* qkv = g_qkv + (size_t)b * KK * 3 * DD + h * DHD;  // row stride 3*DD

    auto load_kv = [&](int s, int jt) {
#pragma unroll
        for (int i = 0; i < 8; i++) {
            int chunk = tid + 128*i;
            int r = chunk >> 4, c4 = chunk & 15;
            const float* src = qkv + (size_t)(jt*64 + r) * (3*DD) + c4*4;
            cpasync16(k_addr + (uint32_t)(s*AK + r*68)*4 + c4*16, src + DD);
            cpasync16(v_addr + (uint32_t)(s*AV + r*72)*4 + c4*16, src + 2*DD);
        }
        cp_commit();
    };

    // Q load + first KV (one cp.async group)
#pragma unroll
    for (int i = 0; i < 8; i++) {
        int chunk = tid + 128*i;
        int r = chunk >> 4, c4 = chunk & 15;
        cpasync16(q_addr + (uint32_t)(r*68)*4 + c4*16,
                  qkv + (size_t)(qb*64 + r) * (3*DD) + c4*4);
    }
    load_kv(0, 0);

    float mrow[2] = {-3.0e38f, -3.0e38f};
    float lrow[2] = {0.f, 0.f};
    float accO[8][4];
#pragma unroll
    for (int ni = 0; ni < 8; ni++)
#pragma unroll
        for (int c = 0; c < 4; c++) accO[ni][c] = 0.f;

    int qrow = wid*16 + g;

    for (int jt = 0; jt <= qb; jt++) {
        if (jt < qb) load_kv((jt+1) & 1, jt+1);
        if (jt < qb) asm volatile("cp.async.wait_group 1;" ::: "memory");
        else         asm volatile("cp.async.wait_group 0;" ::: "memory");
        __syncthreads();

        const float* ks = Ks + (jt & 1)*AK;
        const float* vs = Vs + (jt & 1)*AV;

        // ---- S = Q @ K^T ----
        float accS[8][4];
#pragma unroll
        for (int ni = 0; ni < 8; ni++)
#pragma unroll
            for (int c = 0; c < 4; c++) accS[ni][c] = 0.f;
#pragma unroll
        for (int k8 = 0; k8 < 8; k8++) {
            int k = k8*8;
            float af[4];
            af[0] = Qs[(qrow)*68 + k + tig];
            af[1] = Qs[(qrow+8)*68 + k + tig];
            af[2] = Qs[(qrow)*68 + k + tig + 4];
            af[3] = Qs[(qrow+8)*68 + k + tig + 4];
#pragma unroll
            for (int ni = 0; ni < 8; ni++) {
                float bf[2];
                bf[0] = ks[(8*ni + g)*68 + k + tig];
                bf[1] = ks[(8*ni + g)*68 + k + tig + 4];
                mma8(accS[ni], af, bf);
            }
        }

        // ---- scale + causal mask ----
        bool diag = (jt == qb);
#pragma unroll
        for (int ni = 0; ni < 8; ni++)
#pragma unroll
            for (int c = 0; c < 4; c++) {
                float s = accS[ni][c] * 0.125f;
                if (diag) {
                    int kg = 8*ni + 2*tig + (c & 1);
                    int qg = wid*16 + g + 8*(c >> 1);
                    if (kg > qg) s = -3.0e38f;
                }
                accS[ni][c] = s;
            }

        // ---- online softmax (per thread: rows g, g+8 of warp tile) ----
#pragma unroll
        for (int r = 0; r < 2; r++) {
            float rm = -3.0e38f;
#pragma unroll
            for (int ni = 0; ni < 8; ni++)
                rm = fmaxf(rm, fmaxf(accS[ni][2*r], accS[ni][2*r+1]));
            rm = fmaxf(rm, __shfl_xor_sync(0xffffffffu, rm, 1));
            rm = fmaxf(rm, __shfl_xor_sync(0xffffffffu, rm, 2));
            float mn = fmaxf(mrow[r], rm);
            float corr = __expf(mrow[r] - mn);
            mrow[r] = mn;
            float rs = 0.f;
#pragma unroll
            for (int ni = 0; ni < 8; ni++) {
                float p0 = __expf(accS[ni][2*r]   - mn);
                float p1 = __expf(accS[ni][2*r+1] - mn);
                rs += p0 + p1;
                accS[ni][2*r]   = tf32rn(p0);
                accS[ni][2*r+1] = tf32rn(p1);
            }
            rs += __shfl_xor_sync(0xffffffffu, rs, 1);
            rs += __shfl_xor_sync(0xffffffffu, rs, 2);
            lrow[r] = lrow[r] * corr + rs;
#pragma unroll
            for (int ni = 0; ni < 8; ni++) {
                accO[ni][2*r]   *= corr;
                accO[ni][2*r+1] *= corr;
            }
        }

        // ---- store P to this warp's smem slice ----
#pragma unroll
        for (int ni = 0; ni < 8; ni++) {
            float2 p0; p0.x = accS[ni][0]; p0.y = accS[ni][1];
            float2 p1; p1.x = accS[ni][2]; p1.y = accS[ni][3];
            *(float2*)&Ps[(qrow)*68 + 8*ni + 2*tig]   = p0;
            *(float2*)&Ps[(qrow+8)*68 + 8*ni + 2*tig] = p1;
        }
        __syncwarp();

        // ---- O += P @ V ----
#pragma unroll
        for (int k8 = 0; k8 < 8; k8++) {
            int k = k8*8;
            float af[4];
            af[0] = Ps[(qrow)*68 + k + tig];
            af[1] = Ps[(qrow+8)*68 + k + tig];
            af[2] = Ps[(qrow)*68 + k + tig + 4];
            af[3] = Ps[(qrow+8)*68 + k + tig + 4];
#pragma unroll
            for (int ni = 0; ni < 8; ni++) {
                float bf[2];
                bf[0] = vs[(k + tig)*72 + 8*ni + g];
                bf[1] = vs[(k + tig + 4)*72 + 8*ni + g];
                mma8(accO[ni], af, bf);
            }
        }
        __syncthreads();
    }

    // ---- normalize + write (tf32-rounded: feeds w_o GEMM) ----
    float* op = g_attn + (size_t)b * KK * DD + h * DHD;
#pragma unroll
    for (int r = 0; r < 2; r++) {
        float inv = 1.f / lrow[r];
        int row = qb*64 + wid*16 + g + 8*r;
#pragma unroll
        for (int ni = 0; ni < 8; ni++) {
            float2 o;
            o.x = tf32rn(accO[ni][2*r]   * inv);
            o.y = tf32rn(accO[ni][2*r+1] * inv);
            *(float2*)&op[(size_t)row * DD + 8*ni + 2*tig] = o;
        }
    }
}

// ---------------- launch ----------------
extern "C" void kernel_launch(void* const* d_in, const int* in_sizes, int n_in,
                              void* d_out, int out_size) {
    const float* x        = (const float*)d_in[0];
    const float* w_router = (const float*)d_in[1];
    const float* b_router = (const float*)d_in[2];
    const float* ln1_s    = (const float*)d_in[3];
    const float* ln1_b    = (const float*)d_in[4];
    const float* w_qkv    = (const float*)d_in[5];
    const float* b_qkv    = (const float*)d_in[6];
    const float* w_o      = (const float*)d_in[7];
    const float* b_o      = (const float*)d_in[8];
    const float* ln2_s    = (const float*)d_in[9];
    const float* ln2_b    = (const float*)d_in[10];
    const float* w1       = (const float*)d_in[11];
    const float* b1       = (const float*)d_in[12];
    const float* w2       = (const float*)d_in[13];
    const float* b2       = (const float*)d_in[14];
    float* out = (float*)d_out;

    float *p_h, *p_a, *p_qkv, *p_attn, *p_ffn, *p_wt;
    cudaGetSymbolAddress((void**)&p_h,    g_h);
    cudaGetSymbolAddress((void**)&p_a,    g_a);
    cudaGetSymbolAddress((void**)&p_qkv,  g_qkv);
    cudaGetSymbolAddress((void**)&p_attn, g_attn);
    cudaGetSymbolAddress((void**)&p_ffn,  g_ffn);
    cudaGetSymbolAddress((void**)&p_wt,   g_wt);

    cudaFuncSetAttribute(attn_mma_kernel, cudaFuncAttributeMaxDynamicSharedMemorySize,
                         ATTN2_SMEM);
    cudaFuncSetAttribute(mma_gemm<0>, cudaFuncAttributeMaxDynamicSharedMemorySize, GEMM_SMEM);
    cudaFuncSetAttribute(mma_gemm<1>, cudaFuncAttributeMaxDynamicSharedMemorySize, GEMM_SMEM);
    cudaFuncSetAttribute(mma_gemm<2>, cudaFuncAttributeMaxDynamicSharedMemorySize, GEMM_SMEM);
    cudaFuncSetAttribute(mma_gemm<3>, cudaFuncAttributeMaxDynamicSharedMemorySize, GEMM_SMEM);

    // round all weights to tf32 (RNA) once per launch
    {
        int n;
        n = LL*DD*3*DD/4; round_kernel<<<(n+255)/256, 256>>>(w_qkv, p_wt + WT_QKV, n);
        n = LL*DD*DD/4;   round_kernel<<<(n+255)/256, 256>>>(w_o,   p_wt + WT_O,   n);
        n = LL*DD*FF/4;   round_kernel<<<(n+255)/256, 256>>>(w1,    p_wt + WT_W1,  n);
        n = LL*FF*DD/4;   round_kernel<<<(n+255)/256, 256>>>(w2,    p_wt + WT_W2,  n);
    }

    router_kernel<<<BB*TT/8, 256>>>(x, w_router, b_router);
    topk_kernel<<<BB, 1024>>>();
    gather_kernel<<<BB*KK, 256>>>(x);

    for (int l = 0; l < LL; l++) {
        ln_kernel<<<MROWS, 256>>>(p_h, ln1_s + l*DD, ln1_b + l*DD, p_a);
        mma_gemm<3><<<dim3(3*DD/NT, MROWS/MT), 256, GEMM_SMEM>>>(
            p_a, p_wt + WT_QKV + (size_t)l*3*DD*DD, b_qkv + (size_t)l*3*DD, nullptr,
            p_qkv, DD, 3*DD);
        attn_mma_kernel<<<dim3(KK/64, BB*HH), 128, ATTN2_SMEM>>>();
        mma_gemm<2><<<dim3(DD/NT, MROWS/MT), 256, GEMM_SMEM>>>(
            p_attn, p_wt + WT_O + (size_t)l*DD*DD, b_o + (size_t)l*DD, p_h,
            p_h, DD, DD);
        ln_kernel<<<MROWS, 256>>>(p_h, ln2_s + l*DD, ln2_b + l*DD, p_a);
        mma_gemm<1><<<dim3(FF/NT, MROWS/MT), 256, GEMM_SMEM>>>(
            p_a, p_wt + WT_W1 + (size_t)l*FF*DD, b1 + (size_t)l*FF, nullptr,
            p_ffn, DD, FF);
        mma_gemm<2><<<dim3(DD/NT, MROWS/MT), 256, GEMM_SMEM>>>(
            p_ffn, p_wt + WT_W2 + (size_t)l*DD*FF, b2 + (size_t)l*DD, p_h,
            p_h, FF, DD);
    }

    copy_out_kernel<<<(BB*TT*DD/4)/256, 256>>>(x, out);
    scatter_kernel<<<BB*KK, 256>>>(out);

    long long full = (long long)BB*TT*DD + (long long)BB*KK + (long long)BB*TT;
    if ((long long)out_size >= full) tail_kernel<<<32, 256>>>(out);
}

// round 5
// speedup vs baseline: 3.3381x; 1.0036x over previous
#include <cuda_runtime.h>
#include <math.h>
#include <stdint.h>

#define BB 2
#define TT 4096
#define DD 1024
#define LL 2
#define HH 16
#define FF 4096
#define KK 2048
#define DHD 64
#define MROWS (BB*KK)   // 4096 (batch folded into M)

// ---------------- scratch (static device globals; no allocations) ----------------
__device__ float g_logits[BB*TT];
__device__ int   g_idx[BB*KK];
__device__ int   g_pos[BB*TT];     // token -> k-position (or -1)
__device__ float g_gate[BB*KK];
__device__ float g_h[BB*KK*DD];
__device__ float g_a[BB*KK*DD];
__device__ float g_qkv[BB*KK*3*DD];
__device__ float g_attn[BB*KK*DD];
__device__ float g_ffn[(size_t)BB*KK*FF];

// tf32-rounded weights (same [K,N] layout as inputs)
#define WT_QKV 0
#define WT_O   (LL*DD*3*DD)
#define WT_W1  (WT_O + LL*DD*DD)
#define WT_W2  (WT_W1 + LL*DD*FF)
#define WT_TOT (WT_W2 + LL*FF*DD)
__device__ float g_wt[WT_TOT];

// ---------------- helpers ----------------
__device__ __forceinline__ uint32_t smem_u32(const void* p) {
    uint32_t a;
    asm("{ .reg .u64 t; cvta.to.shared.u64 t, %1; cvt.u32.u64 %0, t; }" : "=r"(a) : "l"(p));
    return a;
}
__device__ __forceinline__ float tf32rn(float x) {
    uint32_t u;
    asm("cvt.rna.tf32.f32 %0, %1;" : "=r"(u) : "f"(x));
    return __uint_as_float(u);
}
__device__ __forceinline__ void cpasync16(uint32_t dst, const void* src) {
    asm volatile("cp.async.cg.shared.global [%0], [%1], 16;" :: "r"(dst), "l"(src) : "memory");
}
__device__ __forceinline__ void cp_commit() {
    asm volatile("cp.async.commit_group;" ::: "memory");
}
__device__ __forceinline__ void mma8(float* d, const float* a, const float* b) {
    asm volatile("mma.sync.aligned.m16n8k8.row.col.f32.tf32.tf32.f32 "
        "{%0,%1,%2,%3}, {%4,%5,%6,%7}, {%8,%9}, {%0,%1,%2,%3};"
        : "+f"(d[0]), "+f"(d[1]), "+f"(d[2]), "+f"(d[3])
        : "r"(__float_as_uint(a[0])), "r"(__float_as_uint(a[1])),
          "r"(__float_as_uint(a[2])), "r"(__float_as_uint(a[3])),
          "r"(__float_as_uint(b[0])), "r"(__float_as_uint(b[1])));
}

__device__ __forceinline__ float gelu_f(float x) {
    float x3 = x * x * x;
    float t = tanhf(0.7978845608028654f * (x + 0.044715f * x3));
    return 0.5f * x * (1.f + t);
}

// ---------------- mma.sync tf32 GEMM: C = A(M x Kd) @ W(Kd x Ntot) + bias ----------------
// CTA tile 128x256, BK=32, 4-stage cp.async pipeline, 8 warps (warp tile 64x64)
#define MT 128
#define NT 256
#define KCH 32
#define AST 36     // A smem row stride (floats): conflict-free fragment loads
#define BST 264    // B smem row stride (floats): conflict-free fragment loads
#define AS_FLOATS (MT*AST)
#define BS_FLOATS (KCH*BST)
#define STG_FLOATS (AS_FLOATS + BS_FLOATS)
#define NSTG 4
#define GEMM_SMEM (NSTG*STG_FLOATS*4)

// EPI: 0 = bias, 1 = bias+gelu+tf32 round, 2 = bias+residual add, 3 = bias+tf32 round
template <int EPI>
__global__ __launch_bounds__(256, 1) void mma_gemm(
    const float* __restrict__ A, const float* __restrict__ W,
    const float* __restrict__ bias, const float* __restrict__ res,
    float* __restrict__ C, int Kd, int Ntot)
{
    extern __shared__ __align__(16) float sm[];
    uint32_t sbase = smem_u32(sm);

    int tid = threadIdx.x;
    int bn = blockIdx.x, bm = blockIdx.y;
    int wid = tid >> 5, lane = tid & 31;
    int wm = wid & 1, wn = wid >> 1;         // warp tile: 64 (M) x 64 (N)
    int g = lane >> 2, tig = lane & 3;

    const float* Ag = A + (size_t)(bm*MT) * Kd;
    const float* Wg = W + (size_t)bn * NT;

    float acc[4][8][4];
#pragma unroll
    for (int mi = 0; mi < 4; mi++)
#pragma unroll
        for (int ni = 0; ni < 8; ni++)
#pragma unroll
            for (int c = 0; c < 4; c++) acc[mi][ni][c] = 0.f;

    int nk = Kd / KCH;

    auto load_stage = [&](int s, int kt) {
        uint32_t ab = sbase + (uint32_t)(s*STG_FLOATS)*4;
        uint32_t bb = ab + AS_FLOATS*4;
#pragma unroll
        for (int i = 0; i < 4; i++) {
            int chunk = tid + 256*i;
            int row = chunk >> 3, cseg = chunk & 7;
            cpasync16(ab + (uint32_t)(row*AST)*4 + cseg*16,
                      Ag + (size_t)row*Kd + kt*KCH + cseg*4);
        }
#pragma unroll
        for (int i = 0; i < 8; i++) {
            int chunk = tid + 256*i;
            int row = chunk >> 6, cseg = chunk & 63;
            cpasync16(bb + (uint32_t)(row*BST)*4 + cseg*16,
                      Wg + (size_t)(kt*KCH + row)*Ntot + cseg*4);
        }
        cp_commit();
    };

    load_stage(0, 0);
    load_stage(1, 1);
    load_stage(2, 2);

    for (int kt = 0; kt < nk; kt++) {
        asm volatile("cp.async.wait_group 2;" ::: "memory");
        __syncthreads();
        if (kt + 3 < nk) load_stage((kt+3) & 3, kt+3);
        else cp_commit();   // empty group keeps wait_group counting aligned

        const float* as = sm + (kt & 3)*STG_FLOATS;
        const float* bs = as + AS_FLOATS;
#pragma unroll
        for (int ks = 0; ks < 4; ks++) {
            int k = ks*8;
            float af[4][4];
#pragma unroll
            for (int mi = 0; mi < 4; mi++) {
                int r = wm*64 + mi*16;
                af[mi][0] = as[(r+g)*AST + k + tig];
                af[mi][1] = as[(r+g+8)*AST + k + tig];
                af[mi][2] = as[(r+g)*AST + k + tig + 4];
                af[mi][3] = as[(r+g+8)*AST + k + tig + 4];
            }
            float bf[8][2];
#pragma unroll
            for (int ni = 0; ni < 8; ni++) {
                int c = wn*64 + ni*8 + g;
                bf[ni][0] = bs[(k+tig)*BST + c];
                bf[ni][1] = bs[(k+tig+4)*BST + c];
            }
#pragma unroll
            for (int mi = 0; mi < 4; mi++)
#pragma unroll
                for (int ni = 0; ni < 8; ni++)
                    mma8(acc[mi][ni], af[mi], bf[ni]);
        }
    }

    // ---- epilogue ----
#pragma unroll
    for (int mi = 0; mi < 4; mi++) {
        int r0 = bm*MT + wm*64 + mi*16 + g;
#pragma unroll
        for (int ni = 0; ni < 8; ni++) {
            int col = bn*NT + wn*64 + ni*8 + tig*2;
            float2 bv = *(const float2*)(bias + col);
#pragma unroll
            for (int hrow = 0; hrow < 2; hrow++) {
                int r = r0 + hrow*8;
                float o0 = acc[mi][ni][hrow*2+0] + bv.x;
                float o1 = acc[mi][ni][hrow*2+1] + bv.y;
                if (EPI == 1) { o0 = tf32rn(gelu_f(o0)); o1 = tf32rn(gelu_f(o1)); }
                if (EPI == 2) {
                    float2 rv = *(const float2*)(res + (size_t)r * Ntot + col);
                    o0 += rv.x; o1 += rv.y;
                }
                if (EPI == 3) { o0 = tf32rn(o0); o1 = tf32rn(o1); }
                float2 ov; ov.x = o0; ov.y = o1;
                *(float2*)(C + (size_t)r * Ntot + col) = ov;
            }
        }
    }
}

// ---------------- fused: weight tf32 rounding + router (independent block ranges) ----------------
#define ROUND_BLOCKS 24576   // WT_TOT/4/256
__global__ void round_router_kernel(
    const float* __restrict__ x, const float* __restrict__ wr, const float* __restrict__ br,
    const float* __restrict__ wq, const float* __restrict__ wo,
    const float* __restrict__ w1s, const float* __restrict__ w2s)
{
    int blk = blockIdx.x;
    if (blk < ROUND_BLOCKS) {
        size_t i = (size_t)blk * 256 + threadIdx.x;   // float4 index into g_wt
        const size_t nQ = (size_t)LL*DD*3*DD/4;
        const size_t nO = nQ + (size_t)LL*DD*DD/4;
        const size_t n1 = nO + (size_t)LL*DD*FF/4;
        const float4* s; size_t off;
        if (i < nQ)      { s = (const float4*)wq;  off = 0; }
        else if (i < nO) { s = (const float4*)wo;  off = nQ; }
        else if (i < n1) { s = (const float4*)w1s; off = nO; }
        else             { s = (const float4*)w2s; off = n1; }
        float4 v = s[i - off];
        v.x = tf32rn(v.x); v.y = tf32rn(v.y); v.z = tf32rn(v.z); v.w = tf32rn(v.w);
        ((float4*)g_wt)[i] = v;
    } else {
        int row  = (blk - ROUND_BLOCKS) * 8 + (threadIdx.x >> 5);
        int lane = threadIdx.x & 31;
        const float4* xr = (const float4*)(x + (size_t)row * DD);
        const float4* wv = (const float4*)wr;
        float s = 0.f;
#pragma unroll
        for (int i = 0; i < 8; i++) {
            int c = lane + i * 32;
            float4 a = xr[c], b = wv[c];
            s += a.x*b.x + a.y*b.y + a.z*b.z + a.w*b.w;
        }
#pragma unroll
        for (int o = 16; o; o >>= 1) s += __shfl_xor_sync(0xffffffffu, s, o);
        if (!lane) g_logits[row] = s + br[0];
    }
}

// ---------------- exact top-K via radix select + scan (also builds inverse map) ----------------
__global__ void topk_kernel() {
    __shared__ unsigned key[TT];
    __shared__ int s_cnt;
    __shared__ int s_scan[1024];
    int b = blockIdx.x, tid = threadIdx.x;

    for (int t = tid; t < TT; t += 1024) {
        unsigned u = __float_as_uint(g_logits[b*TT + t]);
        u = (u & 0x80000000u) ? ~u : (u | 0x80000000u);
        key[t] = u;
    }
    __syncthreads();

    unsigned prefix = 0; int needed = KK;
    for (int bit = 31; bit >= 0; --bit) {
        if (!tid) s_cnt = 0;
        __syncthreads();
        unsigned cand = prefix | (1u << bit);
        unsigned mask = ~((1u << bit) - 1u);
        int loc = 0;
        for (int t = tid; t < TT; t += 1024) loc += ((key[t] & mask) == cand);
#pragma unroll
        for (int o = 16; o; o >>= 1) loc += __shfl_xor_sync(0xffffffffu, loc, o);
        if ((tid & 31) == 0) atomicAdd(&s_cnt, loc);
        __syncthreads();
        int c = s_cnt;
        if (needed <= c) prefix = cand; else needed -= c;
        __syncthreads();
    }
    int base = tid * 4;
    int vals[4]; int run = 0;
#pragma unroll
    for (int i = 0; i < 4; i++) {
        unsigned k2 = key[base + i];
        int gt = (k2 > prefix), eq = (k2 == prefix);
        vals[i] = run;
        run += (gt << 16) | eq;
    }
    s_scan[tid] = run;
    __syncthreads();
    for (int off = 1; off < 1024; off <<= 1) {
        int v = (tid >= off) ? s_scan[tid - off] : 0;
        __syncthreads();
        s_scan[tid] += v;
        __syncthreads();
    }
    int excl = tid ? s_scan[tid - 1] : 0;
#pragma unroll
    for (int i = 0; i < 4; i++) {
        int t = base + i;
        unsigned k2 = key[t];
        int pre = excl + vals[i];
        int gtB = pre >> 16, eqB = pre & 0xFFFF;
        bool sel = (k2 > prefix) || (k2 == prefix && eqB < needed);
        int pos = gtB + min(eqB, needed);
        g_pos[b*TT + t] = sel ? pos : -1;
        if (sel) {
            g_idx[b*KK + pos] = t;
            float lg = g_logits[b*TT + t];
            g_gate[b*KK + pos] = 1.f / (1.f + expf(-lg));
        }
    }
}

// ---------------- fused gather + layer-0 ln1 ----------------
__global__ void gather_ln_kernel(const float* __restrict__ x,
                                 const float* __restrict__ scale,
                                 const float* __restrict__ bias) {
    int row = blockIdx.x, tid = threadIdx.x;
    int b = row / KK;
    int t = g_idx[row];
    float4 v = ((const float4*)(x + ((size_t)b*TT + t) * DD))[tid];
    ((float4*)(g_h + (size_t)row * DD))[tid] = v;

    float s  = v.x + v.y + v.z + v.w;
    float sq = v.x*v.x + v.y*v.y + v.z*v.z + v.w*v.w;
#pragma unroll
    for (int o = 16; o; o >>= 1) {
        s  += __shfl_xor_sync(0xffffffffu, s, o);
        sq += __shfl_xor_sync(0xffffffffu, sq, o);
    }
    __shared__ float ss[8], sq2[8];
    if ((tid & 31) == 0) { ss[tid >> 5] = s; sq2[tid >> 5] = sq; }
    __syncthreads();
    float S = 0.f, SQ = 0.f;
#pragma unroll
    for (int i = 0; i < 8; i++) { S += ss[i]; SQ += sq2[i]; }
    float mean = S * (1.f / DD);
    float var  = SQ * (1.f / DD) - mean * mean;
    float inv  = rsqrtf(var + 1e-5f);
    float4 sc = ((const float4*)scale)[tid];
    float4 bi = ((const float4*)bias)[tid];
    float4 o;
    o.x = tf32rn((v.x - mean) * inv * sc.x + bi.x);
    o.y = tf32rn((v.y - mean) * inv * sc.y + bi.y);
    o.z = tf32rn((v.z - mean) * inv * sc.z + bi.z);
    o.w = tf32rn((v.w - mean) * inv * sc.w + bi.w);
    ((float4*)(g_a + (size_t)row * DD))[tid] = o;
}

// ---------------- single-pass output: copy + gated scatter-add + tail ----------------
#define OUT_MAIN_BLOCKS 8192   // BB*TT*DD/4/256
__global__ void out_kernel(const float* __restrict__ x, float* __restrict__ out) {
    int blk = blockIdx.x;
    if (blk < OUT_MAIN_BLOCKS) {
        size_t i = (size_t)blk * 256 + threadIdx.x;   // float4 index
        int row = (int)(i >> 8);                      // 256 float4 per row
        int b = row >> 12;                            // 4096 rows per batch
        int t = row & (TT - 1);
        float4 v = ((const float4*)x)[i];
        int pos = g_pos[b*TT + t];
        if (pos >= 0) {
            float gg = g_gate[b*KK + pos];
            float4 hv = ((const float4*)(g_h + ((size_t)b*KK + pos) * DD))[i & 255];
            v.x += gg*hv.x; v.y += gg*hv.y; v.z += gg*hv.z; v.w += gg*hv.w;
        }
        ((float4*)out)[i] = v;
    } else {
        int i = (blk - OUT_MAIN_BLOCKS) * 256 + threadIdx.x;
        size_t base = (size_t)BB * TT * DD;
        if (i < BB*KK) out[base + i] = (float)g_idx[i];
        if (i < BB*TT) out[base + BB*KK + i] = g_logits[i];
    }
}

// ---------------- layernorm (output tf32-rounded: feeds GEMM A) ----------------
__global__ void ln_kernel(const float* __restrict__ in, const float* __restrict__ scale,
                          const float* __restrict__ bias, float* __restrict__ out) {
    int row = blockIdx.x, tid = threadIdx.x;
    float4 v = ((const float4*)(in + (size_t)row * DD))[tid];
    float s  = v.x + v.y + v.z + v.w;
    float sq = v.x*v.x + v.y*v.y + v.z*v.z + v.w*v.w;
#pragma unroll
    for (int o = 16; o; o >>= 1) {
        s  += __shfl_xor_sync(0xffffffffu, s, o);
        sq += __shfl_xor_sync(0xffffffffu, sq, o);
    }
    __shared__ float ss[8], sq2[8];
    if ((tid & 31) == 0) { ss[tid >> 5] = s; sq2[tid >> 5] = sq; }
    __syncthreads();
    float S = 0.f, SQ = 0.f;
#pragma unroll
    for (int i = 0; i < 8; i++) { S += ss[i]; SQ += sq2[i]; }
    float mean = S * (1.f / DD);
    float var  = SQ * (1.f / DD) - mean * mean;
    float inv  = rsqrtf(var + 1e-5f);
    float4 sc = ((const float4*)scale)[tid];
    float4 bi = ((const float4*)bias)[tid];
    float4 o;
    o.x = tf32rn((v.x - mean) * inv * sc.x + bi.x);
    o.y = tf32rn((v.y - mean) * inv * sc.y + bi.y);
    o.z = tf32rn((v.z - mean) * inv * sc.z + bi.z);
    o.w = tf32rn((v.w - mean) * inv * sc.w + bi.w);
    ((float4*)(out + (size_t)row * DD))[tid] = o;
}

// ---------------- flash attention: mma.sync tf32, causal, 64x64 tiles ----------------
#define AQ 4352        // 64*68
#define AK 4352
#define AP 4352
#define AV 4608        // 64*72
#define ATTN2_SMEM ((AQ + 2*AK + AP + 2*AV)*4)

__global__ __launch_bounds__(128) void attn_mma_kernel() {
    extern __shared__ __align__(16) float sm[];
    float* Qs = sm;
    float* Ks = sm + AQ;                 // 2 stages
    float* Ps = sm + AQ + 2*AK;
    float* Vs = sm + AQ + 2*AK + AP;     // 2 stages
    uint32_t q_addr = smem_u32(Qs);
    uint32_t k_addr = smem_u32(Ks);
    uint32_t v_addr = smem_u32(Vs);

    int tid = threadIdx.x;
    int wid = tid >> 5, lane = tid & 31;
    int g = lane >> 2, tig = lane & 3;
    int qb = gridDim.x - 1 - blockIdx.x;      // heavy tiles first
    int bh = blockIdx.y;
    int b = bh >> 4, h = bh & 15;
    const float* qkv = g_qkv + (size_t)b * KK * 3 * DD + h * DHD;  // row stride 3*DD

    auto load_kv = [&](int s, int jt) {
#pragma unroll
        for (int i = 0; i < 8; i++) {
            int chunk = tid + 128*i;
            int r = chunk >> 4, c4 = chunk & 15;
            const float* src = qkv + (size_t)(jt*64 + r) * (3*DD) + c4*4;
            cpasync16(k_addr + (uint32_t)(s*AK + r*68)*4 + c4*16, src + DD);
            cpasync16(v_addr + (uint32_t)(s*AV + r*72)*4 + c4*16, src + 2*DD);
        }
        cp_commit();
    };

#pragma unroll
    for (int i = 0; i < 8; i++) {
        int chunk = tid + 128*i;
        int r = chunk >> 4, c4 = chunk & 15;
        cpasync16(q_addr + (uint32_t)(r*68)*4 + c4*16,
                  qkv + (size_t)(qb*64 + r) * (3*DD) + c4*4);
    }
    load_kv(0, 0);

    float mrow[2] = {-3.0e38f, -3.0e38f};
    float lrow[2] = {0.f, 0.f};
    float accO[8][4];
#pragma unroll
    for (int ni = 0; ni < 8; ni++)
#pragma unroll
        for (int c = 0; c < 4; c++) accO[ni][c] = 0.f;

    int qrow = wid*16 + g;

    for (int jt = 0; jt <= qb; jt++) {
        if (jt < qb) load_kv((jt+1) & 1, jt+1);
        if (jt < qb) asm volatile("cp.async.wait_group 1;" ::: "memory");
        else         asm volatile("cp.async.wait_group 0;" ::: "memory");
        __syncthreads();

        const float* ks = Ks + (jt & 1)*AK;
        const float* vs = Vs + (jt & 1)*AV;

        float accS[8][4];
#pragma unroll
        for (int ni = 0; ni < 8; ni++)
#pragma unroll
            for (int c = 0; c < 4; c++) accS[ni][c] = 0.f;
#pragma unroll
        for (int k8 = 0; k8 < 8; k8++) {
            int k = k8*8;
            float af[4];
            af[0] = Qs[(qrow)*68 + k + tig];
            af[1] = Qs[(qrow+8)*68 + k + tig];
            af[2] = Qs[(qrow)*68 + k + tig + 4];
            af[3] = Qs[(qrow+8)*68 + k + tig + 4];
#pragma unroll
            for (int ni = 0; ni < 8; ni++) {
                float bf[2];
                bf[0] = ks[(8*ni + g)*68 + k + tig];
                bf[1] = ks[(8*ni + g)*68 + k + tig + 4];
                mma8(accS[ni], af, bf);
            }
        }

        bool diag = (jt == qb);
#pragma unroll
        for (int ni = 0; ni < 8; ni++)
#pragma unroll
            for (int c = 0; c < 4; c++) {
                float s = accS[ni][c] * 0.125f;
                if (diag) {
                    int kg = 8*ni + 2*tig + (c & 1);
                    int qg = wid*16 + g + 8*(c >> 1);
                    if (kg > qg) s = -3.0e38f;
                }
                accS[ni][c] = s;
            }

#pragma unroll
        for (int r = 0; r < 2; r++) {
            float rm = -3.0e38f;
#pragma unroll
            for (int ni = 0; ni < 8; ni++)
                rm = fmaxf(rm, fmaxf(accS[ni][2*r], accS[ni][2*r+1]));
            rm = fmaxf(rm, __shfl_xor_sync(0xffffffffu, rm, 1));
            rm = fmaxf(rm, __shfl_xor_sync(0xffffffffu, rm, 2));
            float mn = fmaxf(mrow[r], rm);
            float corr = __expf(mrow[r] - mn);
            mrow[r] = mn;
            float rs = 0.f;
#pragma unroll
            for (int ni = 0; ni < 8; ni++) {
                float p0 = __expf(accS[ni][2*r]   - mn);
                float p1 = __expf(accS[ni][2*r+1] - mn);
                rs += p0 + p1;
                accS[ni][2*r]   = tf32rn(p0);
                accS[ni][2*r+1] = tf32rn(p1);
            }
            rs += __shfl_xor_sync(0xffffffffu, rs, 1);
            rs += __shfl_xor_sync(0xffffffffu, rs, 2);
            lrow[r] = lrow[r] * corr + rs;
#pragma unroll
            for (int ni = 0; ni < 8; ni++) {
                accO[ni][2*r]   *= corr;
                accO[ni][2*r+1] *= corr;
            }
        }

#pragma unroll
        for (int ni = 0; ni < 8; ni++) {
            float2 p0; p0.x = accS[ni][0]; p0.y = accS[ni][1];
            float2 p1; p1.x = accS[ni][2]; p1.y = accS[ni][3];
            *(float2*)&Ps[(qrow)*68 + 8*ni + 2*tig]   = p0;
            *(float2*)&Ps[(qrow+8)*68 + 8*ni + 2*tig] = p1;
        }
        __syncwarp();

#pragma unroll
        for (int k8 = 0; k8 < 8; k8++) {
            int k = k8*8;
            float af[4];
            af[0] = Ps[(qrow)*68 + k + tig];
            af[1] = Ps[(qrow+8)*68 + k + tig];
            af[2] = Ps[(qrow)*68 + k + tig + 4];
            af[3] = Ps[(qrow+8)*68 + k + tig + 4];
#pragma unroll
            for (int ni = 0; ni < 8; ni++) {
                float bf[2];
                bf[0] = vs[(k + tig)*72 + 8*ni + g];
                bf[1] = vs[(k + tig + 4)*72 + 8*ni + g];
                mma8(accO[ni], af, bf);
            }
        }
        __syncthreads();
    }

    float* op = g_attn + (size_t)b * KK * DD + h * DHD;
#pragma unroll
    for (int r = 0; r < 2; r++) {
        float inv = 1.f / lrow[r];
        int row = qb*64 + wid*16 + g + 8*r;
#pragma unroll
        for (int ni = 0; ni < 8; ni++) {
            float2 o;
            o.x = tf32rn(accO[ni][2*r]   * inv);
            o.y = tf32rn(accO[ni][2*r+1] * inv);
            *(float2*)&op[(size_t)row * DD + 8*ni + 2*tig] = o;
        }
    }
}

// ---------------- launch ----------------
extern "C" void kernel_launch(void* const* d_in, const int* in_sizes, int n_in,
                              void* d_out, int out_size) {
    const float* x        = (const float*)d_in[0];
    const float* w_router = (const float*)d_in[1];
    const float* b_router = (const float*)d_in[2];
    const float* ln1_s    = (const float*)d_in[3];
    const float* ln1_b    = (const float*)d_in[4];
    const float* w_qkv    = (const float*)d_in[5];
    const float* b_qkv    = (const float*)d_in[6];
    const float* w_o      = (const float*)d_in[7];
    const float* b_o      = (const float*)d_in[8];
    const float* ln2_s    = (const float*)d_in[9];
    const float* ln2_b    = (const float*)d_in[10];
    const float* w1       = (const float*)d_in[11];
    const float* b1       = (const float*)d_in[12];
    const float* w2       = (const float*)d_in[13];
    const float* b2       = (const float*)d_in[14];
    float* out = (float*)d_out;

    float *p_h, *p_a, *p_qkv, *p_attn, *p_ffn, *p_wt;
    cudaGetSymbolAddress((void**)&p_h,    g_h);
    cudaGetSymbolAddress((void**)&p_a,    g_a);
    cudaGetSymbolAddress((void**)&p_qkv,  g_qkv);
    cudaGetSymbolAddress((void**)&p_attn, g_attn);
    cudaGetSymbolAddress((void**)&p_ffn,  g_ffn);
    cudaGetSymbolAddress((void**)&p_wt,   g_wt);

    cudaFuncSetAttribute(attn_mma_kernel, cudaFuncAttributeMaxDynamicSharedMemorySize,
                         ATTN2_SMEM);
    cudaFuncSetAttribute(mma_gemm<1>, cudaFuncAttributeMaxDynamicSharedMemorySize, GEMM_SMEM);
    cudaFuncSetAttribute(mma_gemm<2>, cudaFuncAttributeMaxDynamicSharedMemorySize, GEMM_SMEM);
    cudaFuncSetAttribute(mma_gemm<3>, cudaFuncAttributeMaxDynamicSharedMemorySize, GEMM_SMEM);

    // 1: weight rounding + router (fused, independent)
    round_router_kernel<<<ROUND_BLOCKS + BB*TT/8, 256>>>(
        x, w_router, b_router, w_qkv, w_o, w1, w2);
    // 2: exact top-K
    topk_kernel<<<BB, 1024>>>();
    // 3: gather + layer-0 ln1
    gather_ln_kernel<<<MROWS, 256>>>(x, ln1_s, ln1_b);

    for (int l = 0; l < LL; l++) {
        if (l > 0)
            ln_kernel<<<MROWS, 256>>>(p_h, ln1_s + l*DD, ln1_b + l*DD, p_a);
        // 4 (for l=0): qkv GEMM -> profiled launch
        mma_gemm<3><<<dim3(3*DD/NT, MROWS/MT), 256, GEMM_SMEM>>>(
            p_a, p_wt + WT_QKV + (size_t)l*3*DD*DD, b_qkv + (size_t)l*3*DD, nullptr,
            p_qkv, DD, 3*DD);
        attn_mma_kernel<<<dim3(KK/64, BB*HH), 128, ATTN2_SMEM>>>();
        mma_gemm<2><<<dim3(DD/NT, MROWS/MT), 256, GEMM_SMEM>>>(
            p_attn, p_wt + WT_O + (size_t)l*DD*DD, b_o + (size_t)l*DD, p_h,
            p_h, DD, DD);
        ln_kernel<<<MROWS, 256>>>(p_h, ln2_s + l*DD, ln2_b + l*DD, p_a);
        mma_gemm<1><<<dim3(FF/NT, MROWS/MT), 256, GEMM_SMEM>>>(
            p_a, p_wt + WT_W1 + (size_t)l*FF*DD, b1 + (size_t)l*FF, nullptr,
            p_ffn, DD, FF);
        mma_gemm<2><<<dim3(DD/NT, MROWS/MT), 256, GEMM_SMEM>>>(
            p_ffn, p_wt + WT_W2 + (size_t)l*DD*FF, b2 + (size_t)l*DD, p_h,
            p_h, FF, DD);
    }

    long long full = (long long)BB*TT*DD + (long long)BB*KK + (long long)BB*TT;
    int tail_blocks = ((long long)out_size >= full) ? 32 : 0;
    out_kernel<<<OUT_MAIN_BLOCKS + tail_blocks, 256>>>(x, out);
}